// round 2
// baseline (speedup 1.0000x reference)
#include <cuda_runtime.h>

#define NA 16
#define NEN 128
#define ED 96
#define HE 128
#define MD 32
#define NH 4
#define HD 32

// ---- smem layout (floats) ----
#define OFF_X1   0          // 128*129
#define OFF_KV   16512      // 128*129 (also aliases entity tile [128][96])
#define OFF_W    33024      // 4*16*128
#define OFF_Q    41216      // 16*128
#define OFF_ATTN 43264      // 16*128
#define OFF_OUT  45312      // 16*128
#define OFF_X3   47360      // 16*32
#define OFF_EMF  47872      // 128
#define OFF_RM   48000      // 16
#define OFF_W1   48016      // 16
#define OFF_FLAG 48032      // 4
#define SMEM_FLOATS 48036
#define SMEM_BYTES (SMEM_FLOATS * 4)

struct KParams {
    const float* qs;
    const float* ents;
    const unsigned char* em;
    const float* w[14];   // 2 hypernets x 7 tensors
    float* out;
};

__device__ __forceinline__ float2 ffma2(float2 a, float2 b, float2 c) {
    unsigned long long au = *reinterpret_cast<unsigned long long*>(&a);
    unsigned long long bu = *reinterpret_cast<unsigned long long*>(&b);
    unsigned long long cu = *reinterpret_cast<unsigned long long*>(&c);
    asm("fma.rn.f32x2 %0, %1, %2, %0;" : "+l"(cu) : "l"(au), "l"(bu));
    return *reinterpret_cast<float2*>(&cu);
}

// 128x128 output tile GEMM: A [128 x K] in smem (stride lda), B [K x LDB] in global,
// this thread computes rows r0..r0+7, cols c0..c0+7 into acc (as 4 col-pairs).
template<int K, int LDB>
__device__ __forceinline__ void gemm_8x8(const float* __restrict__ As, int lda,
                                         const float* __restrict__ Bg,
                                         float2 (&acc)[8][4], int r0, int c0) {
#pragma unroll 4
    for (int kk = 0; kk < K; ++kk) {
        const float4* bp = reinterpret_cast<const float4*>(Bg + kk * LDB + c0);
        float4 b0 = __ldg(bp);
        float4 b1 = __ldg(bp + 1);
        float2 bb0 = make_float2(b0.x, b0.y);
        float2 bb1 = make_float2(b0.z, b0.w);
        float2 bb2 = make_float2(b1.x, b1.y);
        float2 bb3 = make_float2(b1.z, b1.w);
#pragma unroll
        for (int i = 0; i < 8; ++i) {
            float av = As[(r0 + i) * lda + kk];
            float2 aa = make_float2(av, av);
            acc[i][0] = ffma2(aa, bb0, acc[i][0]);
            acc[i][1] = ffma2(aa, bb1, acc[i][1]);
            acc[i][2] = ffma2(aa, bb2, acc[i][2]);
            acc[i][3] = ffma2(aa, bb3, acc[i][3]);
        }
    }
}

__global__ void __launch_bounds__(256, 1)
mixer_kernel(KParams P) {
    extern __shared__ float smem[];
    float* s_x1   = smem + OFF_X1;    // stride 129
    float* s_kv   = smem + OFF_KV;    // stride 129 (k then v); ents alias stride 96
    float* s_w    = smem + OFF_W;     // [pair=h*16+q][128]
    float* s_q    = smem + OFF_Q;     // [16][128]
    float* s_attn = smem + OFF_ATTN;  // [16][128]
    float* s_out  = smem + OFF_OUT;   // [16][128]
    float* s_x3   = smem + OFF_X3;    // [16][32]
    float* s_emf  = smem + OFF_EMF;   // [128]
    float* s_rm   = smem + OFF_RM;    // [16]
    float* s_w1m  = smem + OFF_W1;    // [16]
    float* s_flag = smem + OFF_FLAG;

    __shared__ int s_wide;  // 1 if mask elements are 4-byte (int32/float32), 0 if uint8

    const int b   = blockIdx.x;
    const int tid = threadIdx.x;
    const int tx  = tid & 15;
    const int ty  = tid >> 4;
    const int r0  = ty * 8;
    const int c0  = tx * 8;
    const int lane = tid & 31;
    const int warp = tid >> 5;

    // ---- detect mask element width ----
    // Sample 1024 leading 32-bit words. 4-byte elements (int32 0/1 or float32
    // 0.0/1.0) produce only words in {0, 1, 0x3F800000}. Packed uint8 bools
    // (15% density) virtually always produce a word outside that set.
    if (tid == 0) s_wide = 1;
    __syncthreads();
    {
        const unsigned* mw = reinterpret_cast<const unsigned*>(P.em);
        bool ok = true;
#pragma unroll
        for (int s = 0; s < 4; ++s) {
            unsigned w = __ldg(mw + tid + 256 * s);
            ok = ok && (w == 0u || w == 1u || w == 0x3F800000u);
        }
        if (!ok) atomicAnd(&s_wide, 0);
    }
    __syncthreads();
    const bool wide = (s_wide != 0);

    // ---- masks ----
    if (tid < NEN) {
        bool m;
        if (wide) {
            m = __ldg(reinterpret_cast<const unsigned*>(P.em) + (size_t)b * NEN + tid) != 0u;
        } else {
            m = __ldg(P.em + (size_t)b * NEN + tid) != 0;
        }
        s_emf[tid] = m ? 1.0f : 0.0f;
    }
    __syncthreads();
    if (tid == 0) {
        bool all = true;
#pragma unroll
        for (int i = 0; i < NEN; ++i) all = all && (s_emf[i] > 0.5f);
        s_flag[0] = all ? 1.0f : 0.0f;
    }
    __syncthreads();

    for (int p = 0; p < 2; ++p) {
        const float* fc1w = P.w[p * 7 + 0];
        const float* fc1b = P.w[p * 7 + 1];
        const float* inw  = P.w[p * 7 + 2];
        const float* outw = P.w[p * 7 + 3];
        const float* outb = P.w[p * 7 + 4];
        const float* fc2w = P.w[p * 7 + 5];
        const float* fc2b = P.w[p * 7 + 6];

        // ---- load entity tile [128][96] into s_kv region ----
        {
            const float4* eg = reinterpret_cast<const float4*>(P.ents + (size_t)b * NEN * ED);
            float4* es = reinterpret_cast<float4*>(s_kv);
#pragma unroll
            for (int i = tid; i < NEN * ED / 4; i += 256) es[i] = eg[i];
        }
        __syncthreads();

        // ---- x1 = relu(ents @ fc1_w + fc1_b) -> s_x1 ----
        {
            float2 acc[8][4];
#pragma unroll
            for (int i = 0; i < 8; ++i)
#pragma unroll
                for (int j = 0; j < 4; ++j) acc[i][j] = make_float2(0.f, 0.f);
            gemm_8x8<ED, HE>(s_kv, ED, fc1w, acc, r0, c0);
            float4 bb0 = *reinterpret_cast<const float4*>(fc1b + c0);
            float4 bb1 = *reinterpret_cast<const float4*>(fc1b + c0 + 4);
            float bias[8] = {bb0.x, bb0.y, bb0.z, bb0.w, bb1.x, bb1.y, bb1.z, bb1.w};
#pragma unroll
            for (int i = 0; i < 8; ++i) {
                float* row = s_x1 + (r0 + i) * 129 + c0;
#pragma unroll
                for (int j = 0; j < 4; ++j) {
                    row[2 * j + 0] = fmaxf(acc[i][j].x + bias[2 * j + 0], 0.f);
                    row[2 * j + 1] = fmaxf(acc[i][j].y + bias[2 * j + 1], 0.f);
                }
            }
        }
        __syncthreads();

        // ---- q (rows 0..15 of x1 @ in_w[:, 0:128]) scaled by 1/sqrt(HD) ----
        {
            const int r = ty;  // 0..15
            float2 qa[4];
#pragma unroll
            for (int j = 0; j < 4; ++j) qa[j] = make_float2(0.f, 0.f);
#pragma unroll 4
            for (int kk = 0; kk < HE; ++kk) {
                float av = s_x1[r * 129 + kk];
                float2 aa = make_float2(av, av);
                const float4* bp = reinterpret_cast<const float4*>(inw + kk * (3 * HE) + c0);
                float4 b0 = __ldg(bp);
                float4 b1 = __ldg(bp + 1);
                qa[0] = ffma2(aa, make_float2(b0.x, b0.y), qa[0]);
                qa[1] = ffma2(aa, make_float2(b0.z, b0.w), qa[1]);
                qa[2] = ffma2(aa, make_float2(b1.x, b1.y), qa[2]);
                qa[3] = ffma2(aa, make_float2(b1.z, b1.w), qa[3]);
            }
            const float qscale = 0.17677669529663687f;  // 1/sqrt(32)
            float* qr = s_q + r * 128 + c0;
#pragma unroll
            for (int j = 0; j < 4; ++j) {
                qr[2 * j + 0] = qa[j].x * qscale;
                qr[2 * j + 1] = qa[j].y * qscale;
            }
        }

        // ---- k = x1 @ in_w[:, 128:256] -> s_kv ----
        {
            float2 acc[8][4];
#pragma unroll
            for (int i = 0; i < 8; ++i)
#pragma unroll
                for (int j = 0; j < 4; ++j) acc[i][j] = make_float2(0.f, 0.f);
            gemm_8x8<HE, 3 * HE>(s_x1, 129, inw + HE, acc, r0, c0);
#pragma unroll
            for (int i = 0; i < 8; ++i) {
                float* row = s_kv + (r0 + i) * 129 + c0;
#pragma unroll
                for (int j = 0; j < 4; ++j) {
                    row[2 * j + 0] = acc[i][j].x;
                    row[2 * j + 1] = acc[i][j].y;
                }
            }
        }
        __syncthreads();

        // ---- logits + masked softmax -> s_w ----
        for (int it = 0; it < 8; ++it) {
            int pair = warp * 8 + it;
            int h = pair >> 4;
            int q = pair & 15;
            bool qmask = s_emf[q] > 0.5f;
            float lg[4];
#pragma unroll
            for (int j = 0; j < 4; ++j) {
                int k = lane + 32 * j;
                if (qmask || s_emf[k] > 0.5f) {
                    lg[j] = -1e9f;
                } else {
                    const float* qrow = s_q + q * 128 + h * 32;
                    const float* krow = s_kv + k * 129 + h * 32;
                    float s = 0.f;
#pragma unroll
                    for (int d = 0; d < 32; ++d) s += qrow[d] * krow[d];
                    lg[j] = s;
                }
            }
            float mx = fmaxf(fmaxf(lg[0], lg[1]), fmaxf(lg[2], lg[3]));
#pragma unroll
            for (int o = 16; o > 0; o >>= 1)
                mx = fmaxf(mx, __shfl_xor_sync(0xffffffffu, mx, o));
            float e[4];
            float sum = 0.f;
#pragma unroll
            for (int j = 0; j < 4; ++j) { e[j] = __expf(lg[j] - mx); sum += e[j]; }
#pragma unroll
            for (int o = 16; o > 0; o >>= 1)
                sum += __shfl_xor_sync(0xffffffffu, sum, o);
            bool allm = qmask || (s_flag[0] > 0.5f);
            float inv = allm ? 0.f : 1.f / sum;
#pragma unroll
            for (int j = 0; j < 4; ++j)
                s_w[pair * 128 + lane + 32 * j] = e[j] * inv;
        }
        __syncthreads();

        // ---- v = x1 @ in_w[:, 256:384] -> s_kv (overwrite k) ----
        {
            float2 acc[8][4];
#pragma unroll
            for (int i = 0; i < 8; ++i)
#pragma unroll
                for (int j = 0; j < 4; ++j) acc[i][j] = make_float2(0.f, 0.f);
            gemm_8x8<HE, 3 * HE>(s_x1, 129, inw + 2 * HE, acc, r0, c0);
#pragma unroll
            for (int i = 0; i < 8; ++i) {
                float* row = s_kv + (r0 + i) * 129 + c0;
#pragma unroll
                for (int j = 0; j < 4; ++j) {
                    row[2 * j + 0] = acc[i][j].x;
                    row[2 * j + 1] = acc[i][j].y;
                }
            }
        }
        __syncthreads();

        // ---- attn[q][e] = sum_k w[h][q][k] * v[k][h*32+d] ----
        {
            const int q = ty;
            const int h = c0 >> 5;
            const int cc = c0 & 31;
            float a[8];
#pragma unroll
            for (int j = 0; j < 8; ++j) a[j] = 0.f;
            const float* wrow = s_w + (h * 16 + q) * 128;
#pragma unroll 2
            for (int kk = 0; kk < NEN; ++kk) {
                float wv = wrow[kk];
                const float* vr = s_kv + kk * 129 + h * 32 + cc;
#pragma unroll
                for (int j = 0; j < 8; ++j) a[j] = fmaf(wv, vr[j], a[j]);
            }
            float* ar = s_attn + q * 128 + c0;
#pragma unroll
            for (int j = 0; j < 8; ++j) ar[j] = a[j];
        }
        __syncthreads();

        // ---- out = attn @ out_w + out_b, zero masked agents ----
        {
            const int r = ty;
            float2 acc[4];
#pragma unroll
            for (int j = 0; j < 4; ++j) acc[j] = make_float2(0.f, 0.f);
#pragma unroll 4
            for (int kk = 0; kk < HE; ++kk) {
                float av = s_attn[r * 128 + kk];
                float2 aa = make_float2(av, av);
                const float4* bp = reinterpret_cast<const float4*>(outw + kk * HE + c0);
                float4 b0 = __ldg(bp);
                float4 b1 = __ldg(bp + 1);
                acc[0] = ffma2(aa, make_float2(b0.x, b0.y), acc[0]);
                acc[1] = ffma2(aa, make_float2(b0.z, b0.w), acc[1]);
                acc[2] = ffma2(aa, make_float2(b1.x, b1.y), acc[2]);
                acc[3] = ffma2(aa, make_float2(b1.z, b1.w), acc[3]);
            }
            float maskv = (s_emf[r] > 0.5f) ? 0.f : 1.f;
            float4 ob0 = *reinterpret_cast<const float4*>(outb + c0);
            float4 ob1 = *reinterpret_cast<const float4*>(outb + c0 + 4);
            float ob[8] = {ob0.x, ob0.y, ob0.z, ob0.w, ob1.x, ob1.y, ob1.z, ob1.w};
            float* orow = s_out + r * 128 + c0;
#pragma unroll
            for (int j = 0; j < 4; ++j) {
                orow[2 * j + 0] = (acc[j].x + ob[2 * j + 0]) * maskv;
                orow[2 * j + 1] = (acc[j].y + ob[2 * j + 1]) * maskv;
            }
        }
        __syncthreads();

        // ---- x3 = out @ fc2_w + fc2_b, zero masked agents ----
        {
            const int q = ty;
            const int m0 = tx * 2;
            float a0 = 0.f, a1 = 0.f;
#pragma unroll 4
            for (int kk = 0; kk < HE; ++kk) {
                float ov = s_out[q * 128 + kk];
                a0 = fmaf(ov, __ldg(fc2w + kk * MD + m0), a0);
                a1 = fmaf(ov, __ldg(fc2w + kk * MD + m0 + 1), a1);
            }
            float maskv = (s_emf[q] > 0.5f) ? 0.f : 1.f;
            s_x3[q * MD + m0]     = (a0 + fc2b[m0]) * maskv;
            s_x3[q * MD + m0 + 1] = (a1 + fc2b[m0 + 1]) * maskv;
        }
        __syncthreads();

        // ---- per-agent means ----
        if (tid < NA) {
            float s = 0.f;
#pragma unroll
            for (int m = 0; m < MD; ++m) s += s_x3[tid * MD + m];
            float rm = s * (1.f / MD);
            s_rm[tid] = rm;
            if (p == 0) s_w1m[tid] = rm;
        }
        __syncthreads();
    }

    // ---- final mix ----
    if (tid == 0) {
        float vm = 0.f;
#pragma unroll
        for (int q = 0; q < NA; ++q) vm += s_rm[q];
        vm *= (1.f / NA);
        const float* qb = P.qs + (size_t)b * NA;
        float qt = 0.f;
#pragma unroll
        for (int a = 0; a < NA; ++a) qt += qb[a] * fabsf(s_w1m[a]);
        P.out[b] = qt + vm;
    }
}

extern "C" void kernel_launch(void* const* d_in, const int* in_sizes, int n_in,
                              void* d_out, int out_size) {
    KParams P;
    P.qs   = (const float*)d_in[0];
    P.ents = (const float*)d_in[1];
    P.em   = (const unsigned char*)d_in[2];
    for (int i = 0; i < 14; ++i) P.w[i] = (const float*)d_in[3 + i];
    P.out = (float*)d_out;

    cudaFuncSetAttribute(mixer_kernel, cudaFuncAttributeMaxDynamicSharedMemorySize, SMEM_BYTES);

    int nb = in_sizes[0] / NA;  // 1600
    mixer_kernel<<<nb, 256, SMEM_BYTES>>>(P);
}

// round 3
// speedup vs baseline: 1.5953x; 1.5953x over previous
#include <cuda_runtime.h>

#define NA 16
#define NEN 128
#define ED 96
#define HE 128
#define MD 32
#define NH 4
#define HD 32

// ---- smem layout (floats) ----
// x1T, buf2 (entT/kT/vT) are feature-major (transposed), stride 132.
#define OFF_X1T  0          // 128*132
#define OFF_BUF2 16896      // 128*132
#define OFF_Q    33792      // 16*132
#define OFF_W    35904      // 64*128
#define OFF_ATTN 44096      // 16*132
#define OFF_OUT  46208      // 16*132
#define OFF_X3   48320      // 16*32
#define OFF_EMF  48832      // 128
#define OFF_RM   48960      // 16
#define OFF_W1   48976      // 16
#define OFF_FLAG 48992      // pad to 8
#define SMEM_FLOATS 49000
#define SMEM_BYTES (SMEM_FLOATS * 4)

#define TSTRIDE 132

struct KParams {
    const float* qs;
    const float* ents;
    const unsigned char* em;
    const float* w[14];   // 2 hypernets x 7 tensors
    float* out;
};

__device__ __forceinline__ float2 ffma2(float2 a, float2 b, float2 c) {
    unsigned long long au = *reinterpret_cast<unsigned long long*>(&a);
    unsigned long long bu = *reinterpret_cast<unsigned long long*>(&b);
    unsigned long long cu = *reinterpret_cast<unsigned long long*>(&c);
    asm("fma.rn.f32x2 %0, %1, %2, %0;" : "+l"(cu) : "l"(au), "l"(bu));
    return *reinterpret_cast<float2*>(&cu);
}

// Big GEMM: C[128 x 128] = A[128 x K] * B[K x cols], A given transposed in smem
// (AT[k][r], stride TSTRIDE). Warp tile 64x32 (lanes 8x4), thread tile 8x8.
// B is global, double-buffered in registers.
template<int K, int LDB>
__device__ __forceinline__ void gemm_big(const float* __restrict__ AT,
                                         const float* __restrict__ Bg,
                                         float2 (&acc)[8][4], int r0, int c0) {
    constexpr int NB = K / 4;
    float4 b[2][8];
#pragma unroll
    for (int t = 0; t < 4; ++t) {
        const float4* bp = reinterpret_cast<const float4*>(Bg + t * LDB + c0);
        b[0][t * 2]     = __ldg(bp);
        b[0][t * 2 + 1] = __ldg(bp + 1);
    }
#pragma unroll 2
    for (int kb = 0; kb < NB; ++kb) {
        const int cur = kb & 1, nxt = cur ^ 1;
        if (kb + 1 < NB) {
#pragma unroll
            for (int t = 0; t < 4; ++t) {
                const float4* bp = reinterpret_cast<const float4*>(Bg + ((kb + 1) * 4 + t) * LDB + c0);
                b[nxt][t * 2]     = __ldg(bp);
                b[nxt][t * 2 + 1] = __ldg(bp + 1);
            }
        }
#pragma unroll
        for (int t = 0; t < 4; ++t) {
            const int k = kb * 4 + t;
            float4 a0 = *reinterpret_cast<const float4*>(AT + k * TSTRIDE + r0);
            float4 a1 = *reinterpret_cast<const float4*>(AT + k * TSTRIDE + r0 + 4);
            float2 bb0 = make_float2(b[cur][t * 2].x,     b[cur][t * 2].y);
            float2 bb1 = make_float2(b[cur][t * 2].z,     b[cur][t * 2].w);
            float2 bb2 = make_float2(b[cur][t * 2 + 1].x, b[cur][t * 2 + 1].y);
            float2 bb3 = make_float2(b[cur][t * 2 + 1].z, b[cur][t * 2 + 1].w);
            float av[8] = {a0.x, a0.y, a0.z, a0.w, a1.x, a1.y, a1.z, a1.w};
#pragma unroll
            for (int i = 0; i < 8; ++i) {
                float2 aa = make_float2(av[i], av[i]);
                acc[i][0] = ffma2(aa, bb0, acc[i][0]);
                acc[i][1] = ffma2(aa, bb1, acc[i][1]);
                acc[i][2] = ffma2(aa, bb2, acc[i][2]);
                acc[i][3] = ffma2(aa, bb3, acc[i][3]);
            }
        }
    }
}

// Epilogue: store acc (rows r0..r0+7, cols c0..c0+7) TRANSPOSED to dst[c][r],
// stride TSTRIDE, optional bias (8 preloaded values) and relu.
template<bool RELU, bool BIAS>
__device__ __forceinline__ void store_T(float* dst, float2 (&acc)[8][4],
                                        int r0, int c0, const float* bias) {
#pragma unroll
    for (int jc = 0; jc < 8; ++jc) {
        const int c = c0 + jc;
        float vals[8];
#pragma unroll
        for (int i = 0; i < 8; ++i) {
            float x = (jc & 1) ? acc[i][jc >> 1].y : acc[i][jc >> 1].x;
            if (BIAS) x += bias[jc];
            if (RELU) x = fmaxf(x, 0.f);
            vals[i] = x;
        }
        *reinterpret_cast<float4*>(&dst[c * TSTRIDE + r0]) =
            make_float4(vals[0], vals[1], vals[2], vals[3]);
        *reinterpret_cast<float4*>(&dst[c * TSTRIDE + r0 + 4]) =
            make_float4(vals[4], vals[5], vals[6], vals[7]);
    }
}

__global__ void __launch_bounds__(256, 1)
mixer_kernel(KParams P) {
    extern __shared__ float smem[];
    float* s_x1T  = smem + OFF_X1T;
    float* s_buf2 = smem + OFF_BUF2;   // entT, then kT, then vT
    float* s_q    = smem + OFF_Q;      // [16][132] row-major
    float* s_w    = smem + OFF_W;      // [64][128]
    float* s_attn = smem + OFF_ATTN;   // [16][132] row-major
    float* s_out  = smem + OFF_OUT;    // [16][132] row-major
    float* s_x3   = smem + OFF_X3;     // [16][32]
    float* s_emf  = smem + OFF_EMF;    // [128]
    float* s_rm   = smem + OFF_RM;
    float* s_w1m  = smem + OFF_W1;
    float* s_flag = smem + OFF_FLAG;

    __shared__ int s_wide;

    const int b    = blockIdx.x;
    const int tid  = threadIdx.x;
    const int lane = tid & 31;
    const int warp = tid >> 5;

    // big-GEMM mapping: warp tile 64x32, lanes 8x4
    const int warpRow = warp & 1;
    const int warpCol = warp >> 1;
    const int lrow = lane >> 2;
    const int lcol = lane & 3;
    const int r0 = warpRow * 64 + lrow * 8;
    const int c0 = warpCol * 32 + lcol * 8;

    // 16-row mapping
    const int q16 = tid & 15;
    const int cg  = tid >> 4;          // 0..15
    const int cq0 = cg * 8;

    // ---- detect mask element width (same as passing R2 kernel) ----
    if (tid == 0) s_wide = 1;
    __syncthreads();
    {
        const unsigned* mw = reinterpret_cast<const unsigned*>(P.em);
        bool ok = true;
#pragma unroll
        for (int s = 0; s < 4; ++s) {
            unsigned w = __ldg(mw + tid + 256 * s);
            ok = ok && (w == 0u || w == 1u || w == 0x3F800000u);
        }
        if (!ok) atomicAnd(&s_wide, 0);
    }
    __syncthreads();
    const bool wide = (s_wide != 0);

    // ---- masks ----
    if (tid < NEN) {
        bool m;
        if (wide) {
            m = __ldg(reinterpret_cast<const unsigned*>(P.em) + (size_t)b * NEN + tid) != 0u;
        } else {
            m = __ldg(P.em + (size_t)b * NEN + tid) != 0;
        }
        s_emf[tid] = m ? 1.0f : 0.0f;
    }
    __syncthreads();
    if (tid == 0) {
        bool all = true;
#pragma unroll
        for (int i = 0; i < NEN; ++i) all = all && (s_emf[i] > 0.5f);
        s_flag[0] = all ? 1.0f : 0.0f;
    }
    __syncthreads();

    for (int p = 0; p < 2; ++p) {
        const float* fc1w = P.w[p * 7 + 0];
        const float* fc1b = P.w[p * 7 + 1];
        const float* inw  = P.w[p * 7 + 2];
        const float* outw = P.w[p * 7 + 3];
        const float* outb = P.w[p * 7 + 4];
        const float* fc2w = P.w[p * 7 + 5];
        const float* fc2b = P.w[p * 7 + 6];

        // ---- load entities transposed: entT[e][r] into buf2 ----
        {
            const float4* eg = reinterpret_cast<const float4*>(P.ents + (size_t)b * NEN * ED);
#pragma unroll
            for (int i = tid; i < NEN * ED / 4; i += 256) {
                float4 v = __ldg(eg + i);
                int r  = i / (ED / 4);
                int e0 = (i % (ED / 4)) * 4;
                s_buf2[(e0 + 0) * TSTRIDE + r] = v.x;
                s_buf2[(e0 + 1) * TSTRIDE + r] = v.y;
                s_buf2[(e0 + 2) * TSTRIDE + r] = v.z;
                s_buf2[(e0 + 3) * TSTRIDE + r] = v.w;
            }
        }
        __syncthreads();

        // ---- x1 = relu(ents @ fc1_w + b) -> x1T ----
        {
            float2 acc[8][4];
#pragma unroll
            for (int i = 0; i < 8; ++i)
#pragma unroll
                for (int j = 0; j < 4; ++j) acc[i][j] = make_float2(0.f, 0.f);
            gemm_big<ED, HE>(s_buf2, fc1w, acc, r0, c0);
            float4 bb0 = *reinterpret_cast<const float4*>(fc1b + c0);
            float4 bb1 = *reinterpret_cast<const float4*>(fc1b + c0 + 4);
            float bias[8] = {bb0.x, bb0.y, bb0.z, bb0.w, bb1.x, bb1.y, bb1.z, bb1.w};
            store_T<true, true>(s_x1T, acc, r0, c0, bias);
        }
        __syncthreads();

        // ---- q (rows 0..15), scaled by 1/sqrt(HD) -> s_q row-major ----
        {
            float2 qa[4];
#pragma unroll
            for (int j = 0; j < 4; ++j) qa[j] = make_float2(0.f, 0.f);
            const float* Bq = inw + cq0;
#pragma unroll 4
            for (int k = 0; k < HE; ++k) {
                float av = s_x1T[k * TSTRIDE + q16];
                float2 aa = make_float2(av, av);
                const float4* bp = reinterpret_cast<const float4*>(Bq + k * (3 * HE));
                float4 b0 = __ldg(bp);
                float4 b1 = __ldg(bp + 1);
                qa[0] = ffma2(aa, make_float2(b0.x, b0.y), qa[0]);
                qa[1] = ffma2(aa, make_float2(b0.z, b0.w), qa[1]);
                qa[2] = ffma2(aa, make_float2(b1.x, b1.y), qa[2]);
                qa[3] = ffma2(aa, make_float2(b1.z, b1.w), qa[3]);
            }
            const float qscale = 0.17677669529663687f;
            float* qr = s_q + q16 * TSTRIDE + cq0;
            *reinterpret_cast<float4*>(qr) =
                make_float4(qa[0].x * qscale, qa[0].y * qscale, qa[1].x * qscale, qa[1].y * qscale);
            *reinterpret_cast<float4*>(qr + 4) =
                make_float4(qa[2].x * qscale, qa[2].y * qscale, qa[3].x * qscale, qa[3].y * qscale);
        }

        // ---- k = x1 @ in_w[:,128:256] -> kT in buf2 ----
        {
            float2 acc[8][4];
#pragma unroll
            for (int i = 0; i < 8; ++i)
#pragma unroll
                for (int j = 0; j < 4; ++j) acc[i][j] = make_float2(0.f, 0.f);
            gemm_big<HE, 3 * HE>(s_x1T, inw + HE, acc, r0, c0);
            store_T<false, false>(s_buf2, acc, r0, c0, nullptr);
        }
        __syncthreads();

        // ---- logits (raw) -> s_w : 16 warp-tasks (h, eb), K-vec in regs ----
        for (int task = warp; task < 16; task += 8) {
            const int h  = task >> 2;
            const int eb = task & 3;
            const int e  = eb * 32 + lane;
            float2 kvv[16];
#pragma unroll
            for (int d2 = 0; d2 < 16; ++d2) {
                kvv[d2].x = s_buf2[(h * 32 + 2 * d2 + 0) * TSTRIDE + e];
                kvv[d2].y = s_buf2[(h * 32 + 2 * d2 + 1) * TSTRIDE + e];
            }
#pragma unroll 2
            for (int q = 0; q < 16; ++q) {
                const float* qrow = s_q + q * TSTRIDE + h * 32;
                float2 a0 = make_float2(0.f, 0.f), a1 = make_float2(0.f, 0.f);
#pragma unroll
                for (int d4 = 0; d4 < 8; ++d4) {
                    float4 q4 = *reinterpret_cast<const float4*>(qrow + d4 * 4);
                    a0 = ffma2(make_float2(q4.x, q4.y), kvv[d4 * 2 + 0], a0);
                    a1 = ffma2(make_float2(q4.z, q4.w), kvv[d4 * 2 + 1], a1);
                }
                s_w[(h * 16 + q) * 128 + e] = a0.x + a0.y + a1.x + a1.y;
            }
        }
        __syncthreads();

        // ---- masked softmax over s_w (in place) ----
        for (int it = 0; it < 8; ++it) {
            int pair = warp * 8 + it;
            int h = pair >> 4;
            int q = pair & 15;
            (void)h;
            bool qmask = s_emf[q] > 0.5f;
            float lg[4];
#pragma unroll
            for (int j = 0; j < 4; ++j) {
                int k = lane + 32 * j;
                lg[j] = (qmask || s_emf[k] > 0.5f) ? -1e9f : s_w[pair * 128 + k];
            }
            float mx = fmaxf(fmaxf(lg[0], lg[1]), fmaxf(lg[2], lg[3]));
#pragma unroll
            for (int o = 16; o > 0; o >>= 1)
                mx = fmaxf(mx, __shfl_xor_sync(0xffffffffu, mx, o));
            float e[4];
            float sum = 0.f;
#pragma unroll
            for (int j = 0; j < 4; ++j) { e[j] = __expf(lg[j] - mx); sum += e[j]; }
#pragma unroll
            for (int o = 16; o > 0; o >>= 1)
                sum += __shfl_xor_sync(0xffffffffu, sum, o);
            bool allm = qmask || (s_flag[0] > 0.5f);
            float inv = allm ? 0.f : 1.f / sum;
#pragma unroll
            for (int j = 0; j < 4; ++j)
                s_w[pair * 128 + lane + 32 * j] = e[j] * inv;
        }
        __syncthreads();

        // ---- v = x1 @ in_w[:,256:384] -> vT in buf2 (overwrite kT) ----
        {
            float2 acc[8][4];
#pragma unroll
            for (int i = 0; i < 8; ++i)
#pragma unroll
                for (int j = 0; j < 4; ++j) acc[i][j] = make_float2(0.f, 0.f);
            gemm_big<HE, 3 * HE>(s_x1T, inw + 2 * HE, acc, r0, c0);
            store_T<false, false>(s_buf2, acc, r0, c0, nullptr);
        }
        __syncthreads();

        // ---- attn[q][c] = sum_e w[h][q][e] * v[e][c], via vT float4 over e ----
        {
            const int h = cq0 >> 5;
            float2 a2[8];
#pragma unroll
            for (int j = 0; j < 8; ++j) a2[j] = make_float2(0.f, 0.f);
            const float* wrow = s_w + (h * 16 + q16) * 128;
#pragma unroll 4
            for (int e0 = 0; e0 < NEN; e0 += 4) {
                float4 w4 = *reinterpret_cast<const float4*>(wrow + e0);
                float2 wlo = make_float2(w4.x, w4.y);
                float2 whi = make_float2(w4.z, w4.w);
#pragma unroll
                for (int jc = 0; jc < 8; ++jc) {
                    float4 v4 = *reinterpret_cast<const float4*>(&s_buf2[(cq0 + jc) * TSTRIDE + e0]);
                    a2[jc] = ffma2(wlo, make_float2(v4.x, v4.y), a2[jc]);
                    a2[jc] = ffma2(whi, make_float2(v4.z, v4.w), a2[jc]);
                }
            }
            float* ar = s_attn + q16 * TSTRIDE + cq0;
            *reinterpret_cast<float4*>(ar) = make_float4(
                a2[0].x + a2[0].y, a2[1].x + a2[1].y, a2[2].x + a2[2].y, a2[3].x + a2[3].y);
            *reinterpret_cast<float4*>(ar + 4) = make_float4(
                a2[4].x + a2[4].y, a2[5].x + a2[5].y, a2[6].x + a2[6].y, a2[7].x + a2[7].y);
        }
        __syncthreads();

        // ---- out = attn @ out_w + out_b, zero masked agents ----
        {
            float2 acc2[4];
#pragma unroll
            for (int j = 0; j < 4; ++j) acc2[j] = make_float2(0.f, 0.f);
            const float* Bo = outw + cq0;
#pragma unroll 2
            for (int k0 = 0; k0 < HE; k0 += 4) {
                float4 a4 = *reinterpret_cast<const float4*>(&s_attn[q16 * TSTRIDE + k0]);
                float av[4] = {a4.x, a4.y, a4.z, a4.w};
#pragma unroll
                for (int t = 0; t < 4; ++t) {
                    const float4* bp = reinterpret_cast<const float4*>(Bo + (k0 + t) * HE);
                    float4 b0 = __ldg(bp);
                    float4 b1 = __ldg(bp + 1);
                    float2 aa = make_float2(av[t], av[t]);
                    acc2[0] = ffma2(aa, make_float2(b0.x, b0.y), acc2[0]);
                    acc2[1] = ffma2(aa, make_float2(b0.z, b0.w), acc2[1]);
                    acc2[2] = ffma2(aa, make_float2(b1.x, b1.y), acc2[2]);
                    acc2[3] = ffma2(aa, make_float2(b1.z, b1.w), acc2[3]);
                }
            }
            float maskv = (s_emf[q16] > 0.5f) ? 0.f : 1.f;
            float4 ob0 = *reinterpret_cast<const float4*>(outb + cq0);
            float4 ob1 = *reinterpret_cast<const float4*>(outb + cq0 + 4);
            float* orow = s_out + q16 * TSTRIDE + cq0;
            *reinterpret_cast<float4*>(orow) = make_float4(
                (acc2[0].x + ob0.x) * maskv, (acc2[0].y + ob0.y) * maskv,
                (acc2[1].x + ob0.z) * maskv, (acc2[1].y + ob0.w) * maskv);
            *reinterpret_cast<float4*>(orow + 4) = make_float4(
                (acc2[2].x + ob1.x) * maskv, (acc2[2].y + ob1.y) * maskv,
                (acc2[3].x + ob1.z) * maskv, (acc2[3].y + ob1.w) * maskv);
        }
        __syncthreads();

        // ---- x3 = out @ fc2_w + fc2_b, zero masked agents ----
        {
            const int m0 = cg * 2;
            float2 acc2 = make_float2(0.f, 0.f);
#pragma unroll 4
            for (int k0 = 0; k0 < HE; k0 += 4) {
                float4 a4 = *reinterpret_cast<const float4*>(&s_out[q16 * TSTRIDE + k0]);
                float av[4] = {a4.x, a4.y, a4.z, a4.w};
#pragma unroll
                for (int t = 0; t < 4; ++t) {
                    float2 bw = __ldg(reinterpret_cast<const float2*>(fc2w + (k0 + t) * MD + m0));
                    acc2 = ffma2(make_float2(av[t], av[t]), bw, acc2);
                }
            }
            float maskv = (s_emf[q16] > 0.5f) ? 0.f : 1.f;
            s_x3[q16 * MD + m0]     = (acc2.x + fc2b[m0])     * maskv;
            s_x3[q16 * MD + m0 + 1] = (acc2.y + fc2b[m0 + 1]) * maskv;
        }
        __syncthreads();

        // ---- per-agent means ----
        if (tid < NA) {
            float s = 0.f;
#pragma unroll
            for (int m = 0; m < MD; ++m) s += s_x3[tid * MD + m];
            float rm = s * (1.f / MD);
            s_rm[tid] = rm;
            if (p == 0) s_w1m[tid] = rm;
        }
        __syncthreads();
    }

    // ---- final mix ----
    if (tid == 0) {
        float vm = 0.f;
#pragma unroll
        for (int q = 0; q < NA; ++q) vm += s_rm[q];
        vm *= (1.f / NA);
        const float* qb = P.qs + (size_t)b * NA;
        float qt = 0.f;
#pragma unroll
        for (int a = 0; a < NA; ++a) qt += qb[a] * fabsf(s_w1m[a]);
        P.out[b] = qt + vm;
    }
}

extern "C" void kernel_launch(void* const* d_in, const int* in_sizes, int n_in,
                              void* d_out, int out_size) {
    KParams P;
    P.qs   = (const float*)d_in[0];
    P.ents = (const float*)d_in[1];
    P.em   = (const unsigned char*)d_in[2];
    for (int i = 0; i < 14; ++i) P.w[i] = (const float*)d_in[3 + i];
    P.out = (float*)d_out;

    cudaFuncSetAttribute(mixer_kernel, cudaFuncAttributeMaxDynamicSharedMemorySize, SMEM_BYTES);

    int nb = in_sizes[0] / NA;  // 1600
    mixer_kernel<<<nb, 256, SMEM_BYTES>>>(P);
}

// round 4
// speedup vs baseline: 1.6354x; 1.0251x over previous
#include <cuda_runtime.h>

#define NA 16
#define NEN 128
#define ED 96
#define HE 128
#define MD 32
#define NH 4
#define HD 32

// ---- smem layout (floats) ----
#define OFF_X1T  0          // 128*132
#define OFF_BUF2 16896      // 128*132
#define OFF_Q    33792      // 16*132
#define OFF_W    35904      // 64*128
#define OFF_ATTN 44096      // 16*132
#define OFF_OUT  46208      // 16*132
#define OFF_X3   48320      // 16*32
#define OFF_EMF  48832      // 128
#define OFF_RM   48960      // 16
#define OFF_W1   48976      // 16
#define OFF_FLAG 48992      // pad to 8
#define OFF_BST  49000      // 8 warps * 3 stages * 8 k * 32 cols = 6144
#define SMEM_FLOATS 55144
#define SMEM_BYTES (SMEM_FLOATS * 4)

#define TSTRIDE 132

struct KParams {
    const float* qs;
    const float* ents;
    const unsigned char* em;
    const float* w[14];   // 2 hypernets x 7 tensors
    float* out;
};

__device__ __forceinline__ float2 ffma2(float2 a, float2 b, float2 c) {
    unsigned long long au = *reinterpret_cast<unsigned long long*>(&a);
    unsigned long long bu = *reinterpret_cast<unsigned long long*>(&b);
    unsigned long long cu = *reinterpret_cast<unsigned long long*>(&c);
    asm("fma.rn.f32x2 %0, %1, %2, %0;" : "+l"(cu) : "l"(au), "l"(bu));
    return *reinterpret_cast<float2*>(&cu);
}

__device__ __forceinline__ void cp_async16(unsigned saddr, const void* g) {
    asm volatile("cp.async.cg.shared.global [%0], [%1], 16;" :: "r"(saddr), "l"(g));
}

// Staged big GEMM: C[128x128] = A[128xK] * B[KxLDB cols 0..127], A transposed in
// smem (AT[k][r], stride TSTRIDE). Warp tile 64x32 (lanes 8x4), thread 8x8.
// B streamed per-warp through a private 3-stage cp.async ring (8 k-rows/stage).
template<int K, int LDB>
__device__ __forceinline__ void gemm_staged(const float* __restrict__ AT,
                                            const float* __restrict__ Bg,
                                            float* __restrict__ sBw,
                                            float2 (&acc)[8][4],
                                            int r0, int warpCol, int lane) {
    constexpr int NS = K / 8;
    const int lrow8 = lane >> 2;   // 0..7 (copy row)
    const int f4    = lane & 3;    // 0..3 (copy float4)
    const int lcol  = lane & 3;    // compute col group
    const float* gsrc = Bg + (size_t)lrow8 * LDB + warpCol * 32 + f4 * 4;
    unsigned sbase = (unsigned)__cvta_generic_to_shared(sBw) + (lrow8 * 32 + f4 * 4) * 4;

    // issue stage s into ring slot
    auto issue = [&](int s, int slot) {
        const float* g = gsrc + (size_t)s * 8 * LDB;
        unsigned d = sbase + slot * (8 * 32 * 4);
        cp_async16(d, g);
        cp_async16(d + 64, g + 16);
        asm volatile("cp.async.commit_group;" ::: "memory");
    };

    issue(0, 0); issue(1, 1); issue(2, 2);

    const float* Bs0 = sBw + lcol * 8;
    int slot = 0;
#pragma unroll 1
    for (int s = 0; s < NS; ++s) {
        if (s + 2 < NS)      asm volatile("cp.async.wait_group 2;" ::: "memory");
        else if (s + 1 < NS) asm volatile("cp.async.wait_group 1;" ::: "memory");
        else                 asm volatile("cp.async.wait_group 0;" ::: "memory");
        __syncwarp();
        const float* Bs = Bs0 + slot * (8 * 32);
        const float* As = AT + (size_t)s * 8 * TSTRIDE + r0;
#pragma unroll
        for (int t = 0; t < 8; ++t) {
            float4 a0 = *reinterpret_cast<const float4*>(As + t * TSTRIDE);
            float4 a1 = *reinterpret_cast<const float4*>(As + t * TSTRIDE + 4);
            float4 b0 = *reinterpret_cast<const float4*>(Bs + t * 32);
            float4 b1 = *reinterpret_cast<const float4*>(Bs + t * 32 + 4);
            float2 bb0 = make_float2(b0.x, b0.y);
            float2 bb1 = make_float2(b0.z, b0.w);
            float2 bb2 = make_float2(b1.x, b1.y);
            float2 bb3 = make_float2(b1.z, b1.w);
            float av[8] = {a0.x, a0.y, a0.z, a0.w, a1.x, a1.y, a1.z, a1.w};
#pragma unroll
            for (int i = 0; i < 8; ++i) {
                float2 aa = make_float2(av[i], av[i]);
                acc[i][0] = ffma2(aa, bb0, acc[i][0]);
                acc[i][1] = ffma2(aa, bb1, acc[i][1]);
                acc[i][2] = ffma2(aa, bb2, acc[i][2]);
                acc[i][3] = ffma2(aa, bb3, acc[i][3]);
            }
        }
        if (s + 3 < NS) issue(s + 3, slot);
        slot = (slot == 2) ? 0 : slot + 1;
    }
}

// Epilogue: store acc (rows r0..r0+7, cols c0..c0+7) TRANSPOSED to dst[c][r].
template<bool RELU, bool BIAS>
__device__ __forceinline__ void store_T(float* dst, float2 (&acc)[8][4],
                                        int r0, int c0, const float* bias) {
#pragma unroll
    for (int jc = 0; jc < 8; ++jc) {
        const int c = c0 + jc;
        float vals[8];
#pragma unroll
        for (int i = 0; i < 8; ++i) {
            float x = (jc & 1) ? acc[i][jc >> 1].y : acc[i][jc >> 1].x;
            if (BIAS) x += bias[jc];
            if (RELU) x = fmaxf(x, 0.f);
            vals[i] = x;
        }
        *reinterpret_cast<float4*>(&dst[c * TSTRIDE + r0]) =
            make_float4(vals[0], vals[1], vals[2], vals[3]);
        *reinterpret_cast<float4*>(&dst[c * TSTRIDE + r0 + 4]) =
            make_float4(vals[4], vals[5], vals[6], vals[7]);
    }
}

__global__ void __launch_bounds__(256, 1)
mixer_kernel(KParams P) {
    extern __shared__ float smem[];
    float* s_x1T  = smem + OFF_X1T;
    float* s_buf2 = smem + OFF_BUF2;   // entT, then kT, then vT
    float* s_q    = smem + OFF_Q;      // [16][132] row-major
    float* s_w    = smem + OFF_W;      // [64][128]
    float* s_attn = smem + OFF_ATTN;   // [16][132] row-major
    float* s_out  = smem + OFF_OUT;    // [16][132] row-major
    float* s_x3   = smem + OFF_X3;     // [16][32]
    float* s_emf  = smem + OFF_EMF;    // [128]
    float* s_rm   = smem + OFF_RM;
    float* s_w1m  = smem + OFF_W1;
    float* s_flag = smem + OFF_FLAG;
    float* s_bst  = smem + OFF_BST;

    __shared__ int s_wide;

    const int b    = blockIdx.x;
    const int tid  = threadIdx.x;
    const int lane = tid & 31;
    const int warp = tid >> 5;

    // big-GEMM mapping: warp tile 64x32, lanes 8x4
    const int warpRow = warp & 1;
    const int warpCol = warp >> 1;
    const int lrow = lane >> 2;
    const int lcol = lane & 3;
    const int r0 = warpRow * 64 + lrow * 8;
    const int c0 = warpCol * 32 + lcol * 8;
    float* sBw = s_bst + warp * (3 * 8 * 32);

    // 16-row mapping
    const int q16 = tid & 15;
    const int cg  = tid >> 4;          // 0..15
    const int cq0 = cg * 8;

    // ---- detect mask element width ----
    if (tid == 0) s_wide = 1;
    __syncthreads();
    {
        const unsigned* mw = reinterpret_cast<const unsigned*>(P.em);
        bool ok = true;
#pragma unroll
        for (int s = 0; s < 4; ++s) {
            unsigned w = __ldg(mw + tid + 256 * s);
            ok = ok && (w == 0u || w == 1u || w == 0x3F800000u);
        }
        if (!ok) atomicAnd(&s_wide, 0);
    }
    __syncthreads();
    const bool wide = (s_wide != 0);

    // ---- masks ----
    if (tid < NEN) {
        bool m;
        if (wide) {
            m = __ldg(reinterpret_cast<const unsigned*>(P.em) + (size_t)b * NEN + tid) != 0u;
        } else {
            m = __ldg(P.em + (size_t)b * NEN + tid) != 0;
        }
        s_emf[tid] = m ? 1.0f : 0.0f;
    }
    __syncthreads();
    if (tid == 0) {
        bool all = true;
#pragma unroll
        for (int i = 0; i < NEN; ++i) all = all && (s_emf[i] > 0.5f);
        s_flag[0] = all ? 1.0f : 0.0f;
    }
    __syncthreads();

    for (int p = 0; p < 2; ++p) {
        const float* fc1w = P.w[p * 7 + 0];
        const float* fc1b = P.w[p * 7 + 1];
        const float* inw  = P.w[p * 7 + 2];
        const float* outw = P.w[p * 7 + 3];
        const float* outb = P.w[p * 7 + 4];
        const float* fc2w = P.w[p * 7 + 5];
        const float* fc2b = P.w[p * 7 + 6];

        // ---- load entities transposed: entT[e][r] into buf2 ----
        {
            const float4* eg = reinterpret_cast<const float4*>(P.ents + (size_t)b * NEN * ED);
#pragma unroll
            for (int i = tid; i < NEN * ED / 4; i += 256) {
                float4 v = __ldg(eg + i);
                int r  = i / (ED / 4);
                int e0 = (i % (ED / 4)) * 4;
                s_buf2[(e0 + 0) * TSTRIDE + r] = v.x;
                s_buf2[(e0 + 1) * TSTRIDE + r] = v.y;
                s_buf2[(e0 + 2) * TSTRIDE + r] = v.z;
                s_buf2[(e0 + 3) * TSTRIDE + r] = v.w;
            }
        }
        __syncthreads();

        // ---- x1 = relu(ents @ fc1_w + b) -> x1T ----
        {
            float2 acc[8][4];
#pragma unroll
            for (int i = 0; i < 8; ++i)
#pragma unroll
                for (int j = 0; j < 4; ++j) acc[i][j] = make_float2(0.f, 0.f);
            gemm_staged<ED, HE>(s_buf2, fc1w, sBw, acc, r0, warpCol, lane);
            float4 bb0 = *reinterpret_cast<const float4*>(fc1b + c0);
            float4 bb1 = *reinterpret_cast<const float4*>(fc1b + c0 + 4);
            float bias[8] = {bb0.x, bb0.y, bb0.z, bb0.w, bb1.x, bb1.y, bb1.z, bb1.w};
            store_T<true, true>(s_x1T, acc, r0, c0, bias);
        }
        __syncthreads();

        // ---- q (rows 0..15), scaled by 1/sqrt(HD) -> s_q row-major ----
        {
            float2 qa[4];
#pragma unroll
            for (int j = 0; j < 4; ++j) qa[j] = make_float2(0.f, 0.f);
            const float* Bq = inw + cq0;
#pragma unroll 8
            for (int k = 0; k < HE; ++k) {
                float av = s_x1T[k * TSTRIDE + q16];
                float2 aa = make_float2(av, av);
                const float4* bp = reinterpret_cast<const float4*>(Bq + k * (3 * HE));
                float4 b0 = __ldg(bp);
                float4 b1 = __ldg(bp + 1);
                qa[0] = ffma2(aa, make_float2(b0.x, b0.y), qa[0]);
                qa[1] = ffma2(aa, make_float2(b0.z, b0.w), qa[1]);
                qa[2] = ffma2(aa, make_float2(b1.x, b1.y), qa[2]);
                qa[3] = ffma2(aa, make_float2(b1.z, b1.w), qa[3]);
            }
            const float qscale = 0.17677669529663687f;
            float* qr = s_q + q16 * TSTRIDE + cq0;
            *reinterpret_cast<float4*>(qr) =
                make_float4(qa[0].x * qscale, qa[0].y * qscale, qa[1].x * qscale, qa[1].y * qscale);
            *reinterpret_cast<float4*>(qr + 4) =
                make_float4(qa[2].x * qscale, qa[2].y * qscale, qa[3].x * qscale, qa[3].y * qscale);
        }

        // ---- k = x1 @ in_w[:,128:256] -> kT in buf2 ----
        {
            float2 acc[8][4];
#pragma unroll
            for (int i = 0; i < 8; ++i)
#pragma unroll
                for (int j = 0; j < 4; ++j) acc[i][j] = make_float2(0.f, 0.f);
            gemm_staged<HE, 3 * HE>(s_x1T, inw + HE, sBw, acc, r0, warpCol, lane);
            store_T<false, false>(s_buf2, acc, r0, c0, nullptr);
        }
        __syncthreads();

        // ---- logits (raw) -> s_w : 16 warp-tasks (h, eb), K-vec in regs ----
        for (int task = warp; task < 16; task += 8) {
            const int h  = task >> 2;
            const int eb = task & 3;
            const int e  = eb * 32 + lane;
            float2 kvv[16];
#pragma unroll
            for (int d2 = 0; d2 < 16; ++d2) {
                kvv[d2].x = s_buf2[(h * 32 + 2 * d2 + 0) * TSTRIDE + e];
                kvv[d2].y = s_buf2[(h * 32 + 2 * d2 + 1) * TSTRIDE + e];
            }
#pragma unroll 2
            for (int q = 0; q < 16; ++q) {
                const float* qrow = s_q + q * TSTRIDE + h * 32;
                float2 a0 = make_float2(0.f, 0.f), a1 = make_float2(0.f, 0.f);
#pragma unroll
                for (int d4 = 0; d4 < 8; ++d4) {
                    float4 q4 = *reinterpret_cast<const float4*>(qrow + d4 * 4);
                    a0 = ffma2(make_float2(q4.x, q4.y), kvv[d4 * 2 + 0], a0);
                    a1 = ffma2(make_float2(q4.z, q4.w), kvv[d4 * 2 + 1], a1);
                }
                s_w[(h * 16 + q) * 128 + e] = a0.x + a0.y + a1.x + a1.y;
            }
        }
        __syncthreads();

        // ---- masked softmax over s_w (in place) ----
        for (int it = 0; it < 8; ++it) {
            int pair = warp * 8 + it;
            int q = pair & 15;
            bool qmask = s_emf[q] > 0.5f;
            float lg[4];
#pragma unroll
            for (int j = 0; j < 4; ++j) {
                int k = lane + 32 * j;
                lg[j] = (qmask || s_emf[k] > 0.5f) ? -1e9f : s_w[pair * 128 + k];
            }
            float mx = fmaxf(fmaxf(lg[0], lg[1]), fmaxf(lg[2], lg[3]));
#pragma unroll
            for (int o = 16; o > 0; o >>= 1)
                mx = fmaxf(mx, __shfl_xor_sync(0xffffffffu, mx, o));
            float e[4];
            float sum = 0.f;
#pragma unroll
            for (int j = 0; j < 4; ++j) { e[j] = __expf(lg[j] - mx); sum += e[j]; }
#pragma unroll
            for (int o = 16; o > 0; o >>= 1)
                sum += __shfl_xor_sync(0xffffffffu, sum, o);
            bool allm = qmask || (s_flag[0] > 0.5f);
            float inv = allm ? 0.f : 1.f / sum;
#pragma unroll
            for (int j = 0; j < 4; ++j)
                s_w[pair * 128 + lane + 32 * j] = e[j] * inv;
        }
        __syncthreads();

        // ---- v = x1 @ in_w[:,256:384] -> vT in buf2 (overwrite kT) ----
        {
            float2 acc[8][4];
#pragma unroll
            for (int i = 0; i < 8; ++i)
#pragma unroll
                for (int j = 0; j < 4; ++j) acc[i][j] = make_float2(0.f, 0.f);
            gemm_staged<HE, 3 * HE>(s_x1T, inw + 2 * HE, sBw, acc, r0, warpCol, lane);
            store_T<false, false>(s_buf2, acc, r0, c0, nullptr);
        }
        __syncthreads();

        // ---- attn[q][c] = sum_e w[h][q][e] * v[e][c], via vT float4 over e ----
        {
            const int h = cq0 >> 5;
            float2 a2[8];
#pragma unroll
            for (int j = 0; j < 8; ++j) a2[j] = make_float2(0.f, 0.f);
            const float* wrow = s_w + (h * 16 + q16) * 128;
#pragma unroll 4
            for (int e0 = 0; e0 < NEN; e0 += 4) {
                float4 w4 = *reinterpret_cast<const float4*>(wrow + e0);
                float2 wlo = make_float2(w4.x, w4.y);
                float2 whi = make_float2(w4.z, w4.w);
#pragma unroll
                for (int jc = 0; jc < 8; ++jc) {
                    float4 v4 = *reinterpret_cast<const float4*>(&s_buf2[(cq0 + jc) * TSTRIDE + e0]);
                    a2[jc] = ffma2(wlo, make_float2(v4.x, v4.y), a2[jc]);
                    a2[jc] = ffma2(whi, make_float2(v4.z, v4.w), a2[jc]);
                }
            }
            float* ar = s_attn + q16 * TSTRIDE + cq0;
            *reinterpret_cast<float4*>(ar) = make_float4(
                a2[0].x + a2[0].y, a2[1].x + a2[1].y, a2[2].x + a2[2].y, a2[3].x + a2[3].y);
            *reinterpret_cast<float4*>(ar + 4) = make_float4(
                a2[4].x + a2[4].y, a2[5].x + a2[5].y, a2[6].x + a2[6].y, a2[7].x + a2[7].y);
        }
        __syncthreads();

        // ---- out = attn @ out_w + out_b, zero masked agents ----
        {
            float2 acc2[4];
#pragma unroll
            for (int j = 0; j < 4; ++j) acc2[j] = make_float2(0.f, 0.f);
            const float* Bo = outw + cq0;
#pragma unroll 4
            for (int k0 = 0; k0 < HE; k0 += 4) {
                float4 a4 = *reinterpret_cast<const float4*>(&s_attn[q16 * TSTRIDE + k0]);
                float av[4] = {a4.x, a4.y, a4.z, a4.w};
#pragma unroll
                for (int t = 0; t < 4; ++t) {
                    const float4* bp = reinterpret_cast<const float4*>(Bo + (k0 + t) * HE);
                    float4 b0 = __ldg(bp);
                    float4 b1 = __ldg(bp + 1);
                    float2 aa = make_float2(av[t], av[t]);
                    acc2[0] = ffma2(aa, make_float2(b0.x, b0.y), acc2[0]);
                    acc2[1] = ffma2(aa, make_float2(b0.z, b0.w), acc2[1]);
                    acc2[2] = ffma2(aa, make_float2(b1.x, b1.y), acc2[2]);
                    acc2[3] = ffma2(aa, make_float2(b1.z, b1.w), acc2[3]);
                }
            }
            float maskv = (s_emf[q16] > 0.5f) ? 0.f : 1.f;
            float4 ob0 = *reinterpret_cast<const float4*>(outb + cq0);
            float4 ob1 = *reinterpret_cast<const float4*>(outb + cq0 + 4);
            float* orow = s_out + q16 * TSTRIDE + cq0;
            *reinterpret_cast<float4*>(orow) = make_float4(
                (acc2[0].x + ob0.x) * maskv, (acc2[0].y + ob0.y) * maskv,
                (acc2[1].x + ob0.z) * maskv, (acc2[1].y + ob0.w) * maskv);
            *reinterpret_cast<float4*>(orow + 4) = make_float4(
                (acc2[2].x + ob1.x) * maskv, (acc2[2].y + ob1.y) * maskv,
                (acc2[3].x + ob1.z) * maskv, (acc2[3].y + ob1.w) * maskv);
        }
        __syncthreads();

        // ---- x3 = out @ fc2_w + fc2_b, zero masked agents ----
        {
            const int m0 = cg * 2;
            float2 acc2 = make_float2(0.f, 0.f);
#pragma unroll 8
            for (int k0 = 0; k0 < HE; k0 += 4) {
                float4 a4 = *reinterpret_cast<const float4*>(&s_out[q16 * TSTRIDE + k0]);
                float av[4] = {a4.x, a4.y, a4.z, a4.w};
#pragma unroll
                for (int t = 0; t < 4; ++t) {
                    float2 bw = __ldg(reinterpret_cast<const float2*>(fc2w + (k0 + t) * MD + m0));
                    acc2 = ffma2(make_float2(av[t], av[t]), bw, acc2);
                }
            }
            float maskv = (s_emf[q16] > 0.5f) ? 0.f : 1.f;
            s_x3[q16 * MD + m0]     = (acc2.x + fc2b[m0])     * maskv;
            s_x3[q16 * MD + m0 + 1] = (acc2.y + fc2b[m0 + 1]) * maskv;
        }
        __syncthreads();

        // ---- per-agent means ----
        if (tid < NA) {
            float s = 0.f;
#pragma unroll
            for (int m = 0; m < MD; ++m) s += s_x3[tid * MD + m];
            float rm = s * (1.f / MD);
            s_rm[tid] = rm;
            if (p == 0) s_w1m[tid] = rm;
        }
        __syncthreads();
    }

    // ---- final mix ----
    if (tid == 0) {
        float vm = 0.f;
#pragma unroll
        for (int q = 0; q < NA; ++q) vm += s_rm[q];
        vm *= (1.f / NA);
        const float* qb = P.qs + (size_t)b * NA;
        float qt = 0.f;
#pragma unroll
        for (int a = 0; a < NA; ++a) qt += qb[a] * fabsf(s_w1m[a]);
        P.out[b] = qt + vm;
    }
}

extern "C" void kernel_launch(void* const* d_in, const int* in_sizes, int n_in,
                              void* d_out, int out_size) {
    KParams P;
    P.qs   = (const float*)d_in[0];
    P.ents = (const float*)d_in[1];
    P.em   = (const unsigned char*)d_in[2];
    for (int i = 0; i < 14; ++i) P.w[i] = (const float*)d_in[3 + i];
    P.out = (float*)d_out;

    cudaFuncSetAttribute(mixer_kernel, cudaFuncAttributeMaxDynamicSharedMemorySize, SMEM_BYTES);

    int nb = in_sizes[0] / NA;  // 1600
    mixer_kernel<<<nb, 256, SMEM_BYTES>>>(P);
}

// round 6
// speedup vs baseline: 2.0340x; 1.2437x over previous
#include <cuda_runtime.h>
#include <cuda_bf16.h>
#include <cstdint>

#define NA 16
#define NEN 128
#define ED 96
#define HE 128
#define MD 32
#define NH 4
#define HD 32
#define TSTRIDE 132   // fp32 stride (528B) for kv/q/attn/out
#define STRB 132      // u32 stride of bf16 A/B tiles (264 bf16 = 528B)

// ---- smem float offsets ----
#define OFF_A    0        // A tile: 128 x 264 bf16 = 67584B = 16896 floats
#define OFF_B    16896    // B tile: same
#define OFF_KV   33792    // 64 x 132 fp32 = 8448 floats (kT/vT half)
#define OFF_W    42240    // 64 x 128 fp32
#define OFF_Q    50432    // 16 x 132 fp32
#define OFF_EMF  52544    // 128
#define OFF_RM   52672    // 16
#define OFF_W1   52688    // 16
#define OFF_FLAG 52704    // 1
#define SMEM_FLOATS 52712
#define SMEM_BYTES (SMEM_FLOATS * 4)

// overlays inside B region (B dead after v GEMM)
#define BOFF_ATTN 0       // bytes from B base: 16x132x4 = 8448
#define BOFF_OUT  8448
#define BOFF_X3   16896   // 16x32x4 = 2048

struct KParams {
    const float* qs;
    const float* ents;
    const unsigned char* em;
    const float* w[14];
    float* out;
};

static __device__ __forceinline__ void split2(float a, float b, uint32_t& hi, uint32_t& lo) {
    __nv_bfloat16 ha = __float2bfloat16(a), hb = __float2bfloat16(b);
    float ra = a - __bfloat162float(ha), rb = b - __bfloat162float(hb);
    __nv_bfloat16 la = __float2bfloat16(ra), lb = __float2bfloat16(rb);
    hi = (uint32_t)__bfloat16_as_ushort(ha) | ((uint32_t)__bfloat16_as_ushort(hb) << 16);
    lo = (uint32_t)__bfloat16_as_ushort(la) | ((uint32_t)__bfloat16_as_ushort(lb) << 16);
}

static __device__ __forceinline__ float2 ffma2(float2 a, float2 b, float2 c) {
    unsigned long long au = *reinterpret_cast<unsigned long long*>(&a);
    unsigned long long bu = *reinterpret_cast<unsigned long long*>(&b);
    unsigned long long cu = *reinterpret_cast<unsigned long long*>(&c);
    asm("fma.rn.f32x2 %0, %1, %2, %0;" : "+l"(cu) : "l"(au), "l"(bu));
    return *reinterpret_cast<float2*>(&cu);
}

static __device__ __forceinline__ void ldmat4(uint32_t (&r)[4], uint32_t addr) {
    asm volatile("ldmatrix.sync.aligned.m8n8.x4.shared.b16 {%0,%1,%2,%3}, [%4];"
        : "=r"(r[0]), "=r"(r[1]), "=r"(r[2]), "=r"(r[3]) : "r"(addr));
}

static __device__ __forceinline__ void mma16816(float (&d)[4], const uint32_t (&a)[4],
                                                uint32_t b0, uint32_t b1) {
    asm volatile("mma.sync.aligned.m16n8k16.row.col.f32.bf16.bf16.f32 "
        "{%0,%1,%2,%3}, {%4,%5,%6,%7}, {%8,%9}, {%0,%1,%2,%3};"
        : "+f"(d[0]), "+f"(d[1]), "+f"(d[2]), "+f"(d[3])
        : "r"(a[0]), "r"(a[1]), "r"(a[2]), "r"(a[3]), "r"(b0), "r"(b1));
}

// Split-3 bf16 GEMM over A[128 x KH(hi)|KH(lo)] x Bt[128 x KH|KH] (both 528B row stride).
// aL/bL: per-lane ldmatrix base addresses (shared-space), acc = warp tile 32x64.
template<int KH>
static __device__ __forceinline__ void gemm_mma(uint32_t aL, uint32_t bL, float (&acc)[2][8][4]) {
#pragma unroll
    for (int i = 0; i < 2; ++i)
#pragma unroll
        for (int j = 0; j < 8; ++j)
#pragma unroll
            for (int r = 0; r < 4; ++r) acc[i][j][r] = 0.f;
#pragma unroll
    for (int pass = 0; pass < 3; ++pass) {
        const uint32_t aO = (pass == 2) ? (uint32_t)(KH * 2) : 0u;  // bytes
        const uint32_t bO = (pass == 1) ? (uint32_t)(KH * 2) : 0u;
#pragma unroll 2
        for (int kb = 0; kb < KH * 2; kb += 32) {   // kb in bytes, 16 elems/step
            uint32_t a[2][4], bb[4][4];
            ldmat4(a[0], aL + aO + kb);
            ldmat4(a[1], aL + 16u * 528u + aO + kb);
#pragma unroll
            for (int nj = 0; nj < 4; ++nj)
                ldmat4(bb[nj], bL + (uint32_t)nj * 16u * 528u + bO + kb);
#pragma unroll
            for (int mi = 0; mi < 2; ++mi)
#pragma unroll
                for (int nj = 0; nj < 4; ++nj) {
                    mma16816(acc[mi][2 * nj],     a[mi], bb[nj][0], bb[nj][1]);
                    mma16816(acc[mi][2 * nj + 1], a[mi], bb[nj][2], bb[nj][3]);
                }
        }
    }
}

// Fill Bt[n][k] (hi|lo) from row-major W[K][ldb] chunk (128 cols starting at W)
template<int K>
static __device__ __forceinline__ void fillB(uint32_t* Bu, const float* W, int ldb, int tid) {
    constexpr int KP = K / 2;
    for (int idx = tid; idx < KP * 128; idx += 256) {
        int kp = idx >> 7, n = idx & 127;
        float w0 = __ldg(W + (size_t)(2 * kp) * ldb + n);
        float w1 = __ldg(W + (size_t)(2 * kp + 1) * ldb + n);
        uint32_t hi, lo;
        split2(w0, w1, hi, lo);
        Bu[n * STRB + kp]      = hi;
        Bu[n * STRB + KP + kp] = lo;
    }
}

__global__ void __launch_bounds__(256, 1)
mixer_kernel(KParams P) {
    extern __shared__ float smem[];
    char*     smc   = reinterpret_cast<char*>(smem);
    uint32_t* Au    = reinterpret_cast<uint32_t*>(smem + OFF_A);
    uint32_t* Bu    = reinterpret_cast<uint32_t*>(smem + OFF_B);
    float*    s_kv  = smem + OFF_KV;
    float*    s_w   = smem + OFF_W;
    float*    s_q   = smem + OFF_Q;
    float*    s_emf = smem + OFF_EMF;
    float*    s_rm  = smem + OFF_RM;
    float*    s_w1m = smem + OFF_W1;
    float*    s_flag= smem + OFF_FLAG;
    float*    s_attn= reinterpret_cast<float*>(smc + OFF_B * 4 + BOFF_ATTN);
    float*    s_out = reinterpret_cast<float*>(smc + OFF_B * 4 + BOFF_OUT);
    float*    s_x3  = reinterpret_cast<float*>(smc + OFF_B * 4 + BOFF_X3);

    __shared__ int s_wide;

    const int b    = blockIdx.x;
    const int tid  = threadIdx.x;
    const int lane = tid & 31;
    const int warp = tid >> 5;

    // GEMM warp tiling: 4 m-warps x 2 n-warps, warp tile 32x64
    const int mw = warp & 3, nw = warp >> 2;
    const int m0 = mw * 32, n0 = nw * 64;

    // 16-row SIMT mapping
    const int q16 = tid & 15;
    const int cg  = tid >> 4;
    const int cq0 = cg * 8;

    uint32_t smem_u32;
    asm("{ .reg .u64 t; cvta.to.shared.u64 t, %1; cvt.u32.u64 %0, t; }"
        : "=r"(smem_u32) : "l"(smem));
    const uint32_t aBase = smem_u32 + OFF_A * 4;
    const uint32_t bBase = smem_u32 + OFF_B * 4;
    // per-lane ldmatrix bases
    const uint32_t aL = aBase + (uint32_t)(m0 + (lane & 15)) * 528u + (uint32_t)(lane >> 4) * 16u;
    const uint32_t bL = bBase + (uint32_t)(n0 + (lane & 7) + ((lane & 16) >> 1)) * 528u
                              + (uint32_t)((lane >> 3) & 1) * 16u;

    // ---- mask dtype probe ----
    if (tid == 0) s_wide = 1;
    __syncthreads();
    {
        const unsigned* mwp = reinterpret_cast<const unsigned*>(P.em);
        bool ok = true;
#pragma unroll
        for (int s = 0; s < 4; ++s) {
            unsigned w = __ldg(mwp + tid + 256 * s);
            ok = ok && (w == 0u || w == 1u || w == 0x3F800000u);
        }
        if (!ok) atomicAnd(&s_wide, 0);
    }
    __syncthreads();
    const bool wide = (s_wide != 0);

    if (tid < NEN) {
        bool m;
        if (wide) m = __ldg(reinterpret_cast<const unsigned*>(P.em) + (size_t)b * NEN + tid) != 0u;
        else      m = __ldg(P.em + (size_t)b * NEN + tid) != 0;
        s_emf[tid] = m ? 1.0f : 0.0f;
    }
    __syncthreads();
    if (tid == 0) {
        bool all = true;
#pragma unroll
        for (int i = 0; i < NEN; ++i) all = all && (s_emf[i] > 0.5f);
        s_flag[0] = all ? 1.0f : 0.0f;
    }
    __syncthreads();

    float acc[2][8][4];

    for (int p = 0; p < 2; ++p) {
        const float* fc1w = P.w[p * 7 + 0];
        const float* fc1b = P.w[p * 7 + 1];
        const float* inw  = P.w[p * 7 + 2];
        const float* outw = P.w[p * 7 + 3];
        const float* outb = P.w[p * 7 + 4];
        const float* fc2w = P.w[p * 7 + 5];
        const float* fc2b = P.w[p * 7 + 6];

        // ---- 1. fill A (ent hi|lo), B (fc1 weights) ----
        {
            const float2* eg = reinterpret_cast<const float2*>(P.ents + (size_t)b * NEN * ED);
            for (int i = tid; i < NEN * (ED / 2); i += 256) {
                int e = i / (ED / 2), d2 = i % (ED / 2);
                float2 v = __ldg(eg + i);
                uint32_t hi, lo;
                split2(v.x, v.y, hi, lo);
                Au[e * STRB + d2]             = hi;
                Au[e * STRB + (ED / 2) + d2]  = lo;
            }
        }
        fillB<ED>(Bu, fc1w, HE, tid);
        __syncthreads();

        // ---- 2. fc1 GEMM ----
        gemm_mma<ED>(aL, bL, acc);
        __syncthreads();

        // ---- 3. x1 epilogue (relu+bias, re-split into A) + fill B (q weights) ----
#pragma unroll
        for (int mi = 0; mi < 2; ++mi)
#pragma unroll
            for (int nj2 = 0; nj2 < 8; ++nj2) {
                int r = m0 + mi * 16 + (lane >> 2);
                int c = n0 + nj2 * 8 + 2 * (lane & 3);
                float bias0 = __ldg(fc1b + c), bias1 = __ldg(fc1b + c + 1);
                float x0 = fmaxf(acc[mi][nj2][0] + bias0, 0.f);
                float x1v = fmaxf(acc[mi][nj2][1] + bias1, 0.f);
                uint32_t hi, lo;
                split2(x0, x1v, hi, lo);
                Au[r * STRB + (c >> 1)]      = hi;
                Au[r * STRB + 64 + (c >> 1)] = lo;
                x0  = fmaxf(acc[mi][nj2][2] + bias0, 0.f);
                x1v = fmaxf(acc[mi][nj2][3] + bias1, 0.f);
                split2(x0, x1v, hi, lo);
                Au[(r + 8) * STRB + (c >> 1)]      = hi;
                Au[(r + 8) * STRB + 64 + (c >> 1)] = lo;
            }
        fillB<HE>(Bu, inw, 3 * HE, tid);
        __syncthreads();

        // ---- 4. q GEMM ----
        gemm_mma<HE>(aL, bL, acc);
        __syncthreads();

        // ---- 5. q epilogue + fill B (k weights) ----
        if (mw == 0) {
            const float qs = 0.17677669529663687f;  // 1/sqrt(32)
#pragma unroll
            for (int nj2 = 0; nj2 < 8; ++nj2) {
                int r = lane >> 2;
                int c = n0 + nj2 * 8 + 2 * (lane & 3);
                s_q[r * TSTRIDE + c]           = acc[0][nj2][0] * qs;
                s_q[r * TSTRIDE + c + 1]       = acc[0][nj2][1] * qs;
                s_q[(r + 8) * TSTRIDE + c]     = acc[0][nj2][2] * qs;
                s_q[(r + 8) * TSTRIDE + c + 1] = acc[0][nj2][3] * qs;
            }
        }
        fillB<HE>(Bu, inw + HE, 3 * HE, tid);
        __syncthreads();

        // ---- 6. k GEMM ----
        gemm_mma<HE>(aL, bL, acc);
        __syncthreads();

        // ---- 7-10. two-phase kT write + logits ----
#pragma unroll
        for (int ph = 0; ph < 2; ++ph) {
            if (nw == ph) {
#pragma unroll
                for (int mi = 0; mi < 2; ++mi)
#pragma unroll
                    for (int nj2 = 0; nj2 < 8; ++nj2) {
                        int ent = m0 + mi * 16 + (lane >> 2);
                        int f = nj2 * 8 + 2 * (lane & 3);  // local feat 0..63
                        s_kv[f * TSTRIDE + ent]           = acc[mi][nj2][0];
                        s_kv[(f + 1) * TSTRIDE + ent]     = acc[mi][nj2][1];
                        s_kv[f * TSTRIDE + ent + 8]       = acc[mi][nj2][2];
                        s_kv[(f + 1) * TSTRIDE + ent + 8] = acc[mi][nj2][3];
                    }
            }
            __syncthreads();
            // logits for heads ph*2, ph*2+1 : 8 warp tasks
            {
                const int hl = warp >> 2;           // 0..1 local head
                const int h  = ph * 2 + hl;
                const int e  = (warp & 3) * 32 + lane;
                float2 kvv[16];
#pragma unroll
                for (int d2 = 0; d2 < 16; ++d2) {
                    kvv[d2].x = s_kv[(hl * 32 + 2 * d2 + 0) * TSTRIDE + e];
                    kvv[d2].y = s_kv[(hl * 32 + 2 * d2 + 1) * TSTRIDE + e];
                }
#pragma unroll 2
                for (int q = 0; q < 16; ++q) {
                    const float* qrow = s_q + q * TSTRIDE + h * 32;
                    float2 a0 = make_float2(0.f, 0.f), a1 = make_float2(0.f, 0.f);
#pragma unroll
                    for (int d4 = 0; d4 < 8; ++d4) {
                        float4 q4 = *reinterpret_cast<const float4*>(qrow + d4 * 4);
                        a0 = ffma2(make_float2(q4.x, q4.y), kvv[d4 * 2 + 0], a0);
                        a1 = ffma2(make_float2(q4.z, q4.w), kvv[d4 * 2 + 1], a1);
                    }
                    s_w[(h * 16 + q) * 128 + e] = a0.x + a0.y + a1.x + a1.y;
                }
            }
            __syncthreads();
        }

        // ---- 11. masked softmax + fill B (v weights) ----
        for (int it = 0; it < 8; ++it) {
            int pair = warp * 8 + it;
            int q = pair & 15;
            bool qmask = s_emf[q] > 0.5f;
            float lg[4];
#pragma unroll
            for (int j = 0; j < 4; ++j) {
                int k = lane + 32 * j;
                lg[j] = (qmask || s_emf[k] > 0.5f) ? -1e9f : s_w[pair * 128 + k];
            }
            float mx = fmaxf(fmaxf(lg[0], lg[1]), fmaxf(lg[2], lg[3]));
#pragma unroll
            for (int o = 16; o > 0; o >>= 1)
                mx = fmaxf(mx, __shfl_xor_sync(0xffffffffu, mx, o));
            float e[4];
            float sum = 0.f;
#pragma unroll
            for (int j = 0; j < 4; ++j) { e[j] = __expf(lg[j] - mx); sum += e[j]; }
#pragma unroll
            for (int o = 16; o > 0; o >>= 1)
                sum += __shfl_xor_sync(0xffffffffu, sum, o);
            bool allm = qmask || (s_flag[0] > 0.5f);
            float inv = allm ? 0.f : 1.f / sum;
#pragma unroll
            for (int j = 0; j < 4; ++j)
                s_w[pair * 128 + lane + 32 * j] = e[j] * inv;
        }
        fillB<HE>(Bu, inw + 2 * HE, 3 * HE, tid);
        __syncthreads();

        // ---- 12. v GEMM ----
        gemm_mma<HE>(aL, bL, acc);
        __syncthreads();

        // ---- 13-16. two-phase vT write + attnV (s_attn overlays B; B now dead) ----
#pragma unroll
        for (int ph = 0; ph < 2; ++ph) {
            if (nw == ph) {
#pragma unroll
                for (int mi = 0; mi < 2; ++mi)
#pragma unroll
                    for (int nj2 = 0; nj2 < 8; ++nj2) {
                        int ent = m0 + mi * 16 + (lane >> 2);
                        int f = nj2 * 8 + 2 * (lane & 3);
                        s_kv[f * TSTRIDE + ent]           = acc[mi][nj2][0];
                        s_kv[(f + 1) * TSTRIDE + ent]     = acc[mi][nj2][1];
                        s_kv[f * TSTRIDE + ent + 8]       = acc[mi][nj2][2];
                        s_kv[(f + 1) * TSTRIDE + ent + 8] = acc[mi][nj2][3];
                    }
            }
            __syncthreads();
            if ((cg >> 3) == ph) {
                const int h  = cq0 >> 5;
                const int lf = cq0 - ph * 64;   // local feat base
                float2 a2[8];
#pragma unroll
                for (int j = 0; j < 8; ++j) a2[j] = make_float2(0.f, 0.f);
                const float* wrow = s_w + (h * 16 + q16) * 128;
#pragma unroll 4
                for (int e0 = 0; e0 < NEN; e0 += 4) {
                    float4 w4 = *reinterpret_cast<const float4*>(wrow + e0);
                    float2 wlo = make_float2(w4.x, w4.y);
                    float2 whi = make_float2(w4.z, w4.w);
#pragma unroll
                    for (int jc = 0; jc < 8; ++jc) {
                        float4 v4 = *reinterpret_cast<const float4*>(&s_kv[(lf + jc) * TSTRIDE + e0]);
                        a2[jc] = ffma2(wlo, make_float2(v4.x, v4.y), a2[jc]);
                        a2[jc] = ffma2(whi, make_float2(v4.z, v4.w), a2[jc]);
                    }
                }
                float* ar = s_attn + q16 * TSTRIDE + cq0;
                *reinterpret_cast<float4*>(ar) = make_float4(
                    a2[0].x + a2[0].y, a2[1].x + a2[1].y, a2[2].x + a2[2].y, a2[3].x + a2[3].y);
                *reinterpret_cast<float4*>(ar + 4) = make_float4(
                    a2[4].x + a2[4].y, a2[5].x + a2[5].y, a2[6].x + a2[6].y, a2[7].x + a2[7].y);
            }
            __syncthreads();
        }

        // ---- 17. out = attn @ out_w + out_b, masked ----
        {
            float2 acc2[4];
#pragma unroll
            for (int j = 0; j < 4; ++j) acc2[j] = make_float2(0.f, 0.f);
            const float* Bo = outw + cq0;
#pragma unroll 4
            for (int k0 = 0; k0 < HE; k0 += 4) {
                float4 a4 = *reinterpret_cast<const float4*>(&s_attn[q16 * TSTRIDE + k0]);
                float av[4] = {a4.x, a4.y, a4.z, a4.w};
#pragma unroll
                for (int t = 0; t < 4; ++t) {
                    const float4* bp = reinterpret_cast<const float4*>(Bo + (k0 + t) * HE);
                    float4 b0 = __ldg(bp);
                    float4 b1 = __ldg(bp + 1);
                    float2 aa = make_float2(av[t], av[t]);
                    acc2[0] = ffma2(aa, make_float2(b0.x, b0.y), acc2[0]);
                    acc2[1] = ffma2(aa, make_float2(b0.z, b0.w), acc2[1]);
                    acc2[2] = ffma2(aa, make_float2(b1.x, b1.y), acc2[2]);
                    acc2[3] = ffma2(aa, make_float2(b1.z, b1.w), acc2[3]);
                }
            }
            float maskv = (s_emf[q16] > 0.5f) ? 0.f : 1.f;
            float4 ob0 = *reinterpret_cast<const float4*>(outb + cq0);
            float4 ob1 = *reinterpret_cast<const float4*>(outb + cq0 + 4);
            float* orow = s_out + q16 * TSTRIDE + cq0;
            __syncthreads();   // all reads of s_attn done before s_out overlay writes proceed
            *reinterpret_cast<float4*>(orow) = make_float4(
                (acc2[0].x + ob0.x) * maskv, (acc2[0].y + ob0.y) * maskv,
                (acc2[1].x + ob0.z) * maskv, (acc2[1].y + ob0.w) * maskv);
            *reinterpret_cast<float4*>(orow + 4) = make_float4(
                (acc2[2].x + ob1.x) * maskv, (acc2[2].y + ob1.y) * maskv,
                (acc2[3].x + ob1.z) * maskv, (acc2[3].y + ob1.w) * maskv);
        }
        __syncthreads();

        // ---- 18. x3 = out @ fc2_w + fc2_b, masked ----
        {
            const int m0x = cg * 2;
            float2 acc2 = make_float2(0.f, 0.f);
#pragma unroll 8
            for (int k0 = 0; k0 < HE; k0 += 4) {
                float4 a4 = *reinterpret_cast<const float4*>(&s_out[q16 * TSTRIDE + k0]);
                float av[4] = {a4.x, a4.y, a4.z, a4.w};
#pragma unroll
                for (int t = 0; t < 4; ++t) {
                    float2 bw = __ldg(reinterpret_cast<const float2*>(fc2w + (k0 + t) * MD + m0x));
                    acc2 = ffma2(make_float2(av[t], av[t]), bw, acc2);
                }
            }
            float maskv = (s_emf[q16] > 0.5f) ? 0.f : 1.f;
            s_x3[q16 * MD + m0x]     = (acc2.x + fc2b[m0x])     * maskv;
            s_x3[q16 * MD + m0x + 1] = (acc2.y + fc2b[m0x + 1]) * maskv;
        }
        __syncthreads();

        if (tid < NA) {
            float s = 0.f;
#pragma unroll
            for (int m = 0; m < MD; ++m) s += s_x3[tid * MD + m];
            float rm = s * (1.f / MD);
            s_rm[tid] = rm;
            if (p == 0) s_w1m[tid] = rm;
        }
        __syncthreads();
    }

    if (tid == 0) {
        float vm = 0.f;
#pragma unroll
        for (int q = 0; q < NA; ++q) vm += s_rm[q];
        vm *= (1.f / NA);
        const float* qb = P.qs + (size_t)b * NA;
        float qt = 0.f;
#pragma unroll
        for (int a = 0; a < NA; ++a) qt += qb[a] * fabsf(s_w1m[a]);
        P.out[b] = qt + vm;
    }
}

extern "C" void kernel_launch(void* const* d_in, const int* in_sizes, int n_in,
                              void* d_out, int out_size) {
    KParams P;
    P.qs   = (const float*)d_in[0];
    P.ents = (const float*)d_in[1];
    P.em   = (const unsigned char*)d_in[2];
    for (int i = 0; i < 14; ++i) P.w[i] = (const float*)d_in[3 + i];
    P.out = (float*)d_out;

    cudaFuncSetAttribute(mixer_kernel, cudaFuncAttributeMaxDynamicSharedMemorySize, SMEM_BYTES);

    int nb = in_sizes[0] / NA;  // 1600
    mixer_kernel<<<nb, 256, SMEM_BYTES>>>(P);
}

// round 7
// speedup vs baseline: 2.3149x; 1.1381x over previous
#include <cuda_runtime.h>
#include <cuda_bf16.h>
#include <cstdint>

#define NA 16
#define NEN 128
#define ED 96
#define HE 128
#define MD 32
#define NH 4
#define HD 32
#define TSTRIDE 132   // fp32 stride (528B) for kv/q/attn/out
#define STRB 132      // u32 stride of bf16 A/B tiles (264 bf16 = 528B)

// ---- smem float offsets ----
#define OFF_A    0        // A tile: 128 x 264 bf16 = 67584B = 16896 floats
#define OFF_B    16896    // B tile: same
#define OFF_KV   33792    // 64 x 132 fp32 = 8448 floats (kT/vT half)
#define OFF_W    42240    // 64 x 128 fp32
#define OFF_Q    50432    // 16 x 132 fp32
#define OFF_EMF  52544    // 128
#define OFF_RM   52672    // 16
#define OFF_W1   52688    // 16
#define OFF_FLAG 52704    // 1
#define SMEM_FLOATS 52712
#define SMEM_BYTES (SMEM_FLOATS * 4)

// overlays inside B region (B dead after v GEMM)
#define BOFF_ATTN 0
#define BOFF_OUT  8448
#define BOFF_X3   16896

#define TILE_U32 (128 * 132)

struct KParams {
    const float* qs;
    const float* ents;
    const unsigned char* em;
    const float* w[14];
    float* out;
};

// pre-split, pre-laid-out bf16 weight tiles: [p*4 + {fc1,q,k,v}]
__device__ uint32_t g_wt[8 * TILE_U32];

static __device__ __forceinline__ void split2(float a, float b, uint32_t& hi, uint32_t& lo) {
    __nv_bfloat16 ha = __float2bfloat16(a), hb = __float2bfloat16(b);
    float ra = a - __bfloat162float(ha), rb = b - __bfloat162float(hb);
    __nv_bfloat16 la = __float2bfloat16(ra), lb = __float2bfloat16(rb);
    hi = (uint32_t)__bfloat16_as_ushort(ha) | ((uint32_t)__bfloat16_as_ushort(hb) << 16);
    lo = (uint32_t)__bfloat16_as_ushort(la) | ((uint32_t)__bfloat16_as_ushort(lb) << 16);
}

static __device__ __forceinline__ float2 ffma2(float2 a, float2 b, float2 c) {
    unsigned long long au = *reinterpret_cast<unsigned long long*>(&a);
    unsigned long long bu = *reinterpret_cast<unsigned long long*>(&b);
    unsigned long long cu = *reinterpret_cast<unsigned long long*>(&c);
    asm("fma.rn.f32x2 %0, %1, %2, %0;" : "+l"(cu) : "l"(au), "l"(bu));
    return *reinterpret_cast<float2*>(&cu);
}

static __device__ __forceinline__ void ldmat4(uint32_t (&r)[4], uint32_t addr) {
    asm volatile("ldmatrix.sync.aligned.m8n8.x4.shared.b16 {%0,%1,%2,%3}, [%4];"
        : "=r"(r[0]), "=r"(r[1]), "=r"(r[2]), "=r"(r[3]) : "r"(addr));
}

static __device__ __forceinline__ void mma16816(float (&d)[4], const uint32_t (&a)[4],
                                                uint32_t b0, uint32_t b1) {
    asm volatile("mma.sync.aligned.m16n8k16.row.col.f32.bf16.bf16.f32 "
        "{%0,%1,%2,%3}, {%4,%5,%6,%7}, {%8,%9}, {%0,%1,%2,%3};"
        : "+f"(d[0]), "+f"(d[1]), "+f"(d[2]), "+f"(d[3])
        : "r"(a[0]), "r"(a[1]), "r"(a[2]), "r"(a[3]), "r"(b0), "r"(b1));
}

static __device__ __forceinline__ void cp_async16(uint32_t saddr, const void* g) {
    asm volatile("cp.async.cg.shared.global [%0], [%1], 16;" :: "r"(saddr), "l"(g));
}

// bulk-copy one pre-laid-out B tile image into smem via cp.async
static __device__ __forceinline__ void copyB_async(uint32_t bBase, const uint32_t* g, int tid) {
#pragma unroll 1
    for (int i = tid; i < TILE_U32 / 4; i += 256)
        cp_async16(bBase + (uint32_t)i * 16u, g + i * 4);
    asm volatile("cp.async.commit_group;" ::: "memory");
}
#define CP_WAIT0() asm volatile("cp.async.wait_group 0;" ::: "memory")

// Split-3 bf16 GEMM over A[128 x K(hi)|K(lo) bf16] x Bt[128 x K|K] (528B row stride).
template<int K>
static __device__ __forceinline__ void gemm_mma(uint32_t aL, uint32_t bL, float (&acc)[2][8][4]) {
#pragma unroll
    for (int i = 0; i < 2; ++i)
#pragma unroll
        for (int j = 0; j < 8; ++j)
#pragma unroll
            for (int r = 0; r < 4; ++r) acc[i][j][r] = 0.f;
#pragma unroll
    for (int pass = 0; pass < 3; ++pass) {
        const uint32_t aO = (pass == 2) ? (uint32_t)(K * 2) : 0u;  // bytes
        const uint32_t bO = (pass == 1) ? (uint32_t)(K * 2) : 0u;
#pragma unroll 2
        for (int kb = 0; kb < K * 2; kb += 32) {
            uint32_t a[2][4], bb[4][4];
            ldmat4(a[0], aL + aO + kb);
            ldmat4(a[1], aL + 16u * 528u + aO + kb);
#pragma unroll
            for (int nj = 0; nj < 4; ++nj)
                ldmat4(bb[nj], bL + (uint32_t)nj * 16u * 528u + bO + kb);
#pragma unroll
            for (int mi = 0; mi < 2; ++mi)
#pragma unroll
                for (int nj = 0; nj < 4; ++nj) {
                    mma16816(acc[mi][2 * nj],     a[mi], bb[nj][0], bb[nj][1]);
                    mma16816(acc[mi][2 * nj + 1], a[mi], bb[nj][2], bb[nj][3]);
                }
        }
    }
}

// ---- prep kernel: split weights into tile-image layout, once per launch ----
__global__ void prep_kernel(KParams P) {
    const int t = blockIdx.y;          // 0..7
    const int p = t >> 2, ch = t & 3;
    const float* W; int ldb, KP;
    if (ch == 0) { W = P.w[p * 7 + 0]; ldb = HE;     KP = ED / 2; }
    else         { W = P.w[p * 7 + 2] + (ch - 1) * HE; ldb = 3 * HE; KP = 64; }
    uint32_t* dst = g_wt + t * TILE_U32;
    const int nkpb = KP >> 2;
    int idx = blockIdx.x * blockDim.x + threadIdx.x;
    if (idx >= 128 * nkpb) return;
    int n = idx / nkpb, kpb = idx % nkpb;
    uint32_t hi[4], lo[4];
#pragma unroll
    for (int j = 0; j < 4; ++j) {
        int kp = kpb * 4 + j;
        float w0 = __ldg(W + (size_t)(2 * kp) * ldb + n);
        float w1 = __ldg(W + (size_t)(2 * kp + 1) * ldb + n);
        split2(w0, w1, hi[j], lo[j]);
    }
    *reinterpret_cast<uint4*>(dst + n * STRB + kpb * 4)      = make_uint4(hi[0], hi[1], hi[2], hi[3]);
    *reinterpret_cast<uint4*>(dst + n * STRB + KP + kpb * 4) = make_uint4(lo[0], lo[1], lo[2], lo[3]);
}

__global__ void __launch_bounds__(256, 1)
mixer_kernel(KParams P) {
    extern __shared__ float smem[];
    char*     smc   = reinterpret_cast<char*>(smem);
    uint32_t* Au    = reinterpret_cast<uint32_t*>(smem + OFF_A);
    float*    s_kv  = smem + OFF_KV;
    float*    s_w   = smem + OFF_W;
    float*    s_q   = smem + OFF_Q;
    float*    s_emf = smem + OFF_EMF;
    float*    s_rm  = smem + OFF_RM;
    float*    s_w1m = smem + OFF_W1;
    float*    s_flag= smem + OFF_FLAG;
    float*    s_attn= reinterpret_cast<float*>(smc + OFF_B * 4 + BOFF_ATTN);
    float*    s_out = reinterpret_cast<float*>(smc + OFF_B * 4 + BOFF_OUT);
    float*    s_x3  = reinterpret_cast<float*>(smc + OFF_B * 4 + BOFF_X3);

    __shared__ int s_wide;

    const int b    = blockIdx.x;
    const int tid  = threadIdx.x;
    const int lane = tid & 31;
    const int warp = tid >> 5;

    const int mw = warp & 3, nw = warp >> 2;
    const int m0 = mw * 32, n0 = nw * 64;

    const int q16 = tid & 15;
    const int cg  = tid >> 4;
    const int cq0 = cg * 8;

    uint32_t smem_u32;
    asm("{ .reg .u64 t; cvta.to.shared.u64 t, %1; cvt.u32.u64 %0, t; }"
        : "=r"(smem_u32) : "l"(smem));
    const uint32_t aBase = smem_u32 + OFF_A * 4;
    const uint32_t bBase = smem_u32 + OFF_B * 4;
    const uint32_t aL = aBase + (uint32_t)(m0 + (lane & 15)) * 528u + (uint32_t)(lane >> 4) * 16u;
    const uint32_t bL = bBase + (uint32_t)(n0 + (lane & 7) + ((lane & 16) >> 1)) * 528u
                              + (uint32_t)((lane >> 3) & 1) * 16u;

    // ---- mask dtype probe ----
    if (tid == 0) s_wide = 1;
    __syncthreads();
    {
        const unsigned* mwp = reinterpret_cast<const unsigned*>(P.em);
        bool ok = true;
#pragma unroll
        for (int s = 0; s < 4; ++s) {
            unsigned w = __ldg(mwp + tid + 256 * s);
            ok = ok && (w == 0u || w == 1u || w == 0x3F800000u);
        }
        if (!ok) atomicAnd(&s_wide, 0);
    }
    __syncthreads();
    const bool wide = (s_wide != 0);

    if (tid < NEN) {
        bool m;
        if (wide) m = __ldg(reinterpret_cast<const unsigned*>(P.em) + (size_t)b * NEN + tid) != 0u;
        else      m = __ldg(P.em + (size_t)b * NEN + tid) != 0;
        s_emf[tid] = m ? 1.0f : 0.0f;
    }
    __syncthreads();
    if (tid == 0) {
        bool all = true;
#pragma unroll
        for (int i = 0; i < NEN; ++i) all = all && (s_emf[i] > 0.5f);
        s_flag[0] = all ? 1.0f : 0.0f;
    }
    __syncthreads();

    float acc[2][8][4];

    for (int p = 0; p < 2; ++p) {
        const float* fc1b = P.w[p * 7 + 1];
        const float* outw = P.w[p * 7 + 3];
        const float* outb = P.w[p * 7 + 4];
        const float* fc2w = P.w[p * 7 + 5];
        const float* fc2b = P.w[p * 7 + 6];
        const uint32_t* wt = g_wt + (p * 4) * TILE_U32;

        // ---- 1. cp.async B(fc1) + fill A (ent hi|lo) ----
        copyB_async(bBase, wt, tid);
        {
            const float2* eg = reinterpret_cast<const float2*>(P.ents + (size_t)b * NEN * ED);
            for (int i = tid; i < NEN * (ED / 2); i += 256) {
                int e = i / (ED / 2), d2 = i % (ED / 2);
                float2 v = __ldg(eg + i);
                uint32_t hi, lo;
                split2(v.x, v.y, hi, lo);
                Au[e * STRB + d2]            = hi;
                Au[e * STRB + (ED / 2) + d2] = lo;
            }
        }
        CP_WAIT0();
        __syncthreads();

        // ---- 2. fc1 GEMM ----
        gemm_mma<ED>(aL, bL, acc);
        __syncthreads();

        // ---- 3. cp.async B(q) + x1 epilogue (relu+bias, re-split into A) ----
        copyB_async(bBase, wt + TILE_U32, tid);
#pragma unroll
        for (int mi = 0; mi < 2; ++mi)
#pragma unroll
            for (int nj2 = 0; nj2 < 8; ++nj2) {
                int r = m0 + mi * 16 + (lane >> 2);
                int c = n0 + nj2 * 8 + 2 * (lane & 3);
                float bias0 = __ldg(fc1b + c), bias1 = __ldg(fc1b + c + 1);
                float x0 = fmaxf(acc[mi][nj2][0] + bias0, 0.f);
                float x1v = fmaxf(acc[mi][nj2][1] + bias1, 0.f);
                uint32_t hi, lo;
                split2(x0, x1v, hi, lo);
                Au[r * STRB + (c >> 1)]      = hi;
                Au[r * STRB + 64 + (c >> 1)] = lo;
                x0  = fmaxf(acc[mi][nj2][2] + bias0, 0.f);
                x1v = fmaxf(acc[mi][nj2][3] + bias1, 0.f);
                split2(x0, x1v, hi, lo);
                Au[(r + 8) * STRB + (c >> 1)]      = hi;
                Au[(r + 8) * STRB + 64 + (c >> 1)] = lo;
            }
        CP_WAIT0();
        __syncthreads();

        // ---- 4. q GEMM ----
        gemm_mma<HE>(aL, bL, acc);
        __syncthreads();

        // ---- 5. cp.async B(k) + q epilogue ----
        copyB_async(bBase, wt + 2 * TILE_U32, tid);
        if (mw == 0) {
            const float qs = 0.17677669529663687f;  // 1/sqrt(32)
#pragma unroll
            for (int nj2 = 0; nj2 < 8; ++nj2) {
                int r = lane >> 2;
                int c = n0 + nj2 * 8 + 2 * (lane & 3);
                s_q[r * TSTRIDE + c]           = acc[0][nj2][0] * qs;
                s_q[r * TSTRIDE + c + 1]       = acc[0][nj2][1] * qs;
                s_q[(r + 8) * TSTRIDE + c]     = acc[0][nj2][2] * qs;
                s_q[(r + 8) * TSTRIDE + c + 1] = acc[0][nj2][3] * qs;
            }
        }
        CP_WAIT0();
        __syncthreads();

        // ---- 6. k GEMM ----
        gemm_mma<HE>(aL, bL, acc);
        __syncthreads();

        // ---- 7. cp.async B(v) overlapped with kT writes + logits + softmax ----
        copyB_async(bBase, wt + 3 * TILE_U32, tid);
#pragma unroll
        for (int ph = 0; ph < 2; ++ph) {
            if (nw == ph) {
#pragma unroll
                for (int mi = 0; mi < 2; ++mi)
#pragma unroll
                    for (int nj2 = 0; nj2 < 8; ++nj2) {
                        int ent = m0 + mi * 16 + (lane >> 2);
                        int f = nj2 * 8 + 2 * (lane & 3);
                        s_kv[f * TSTRIDE + ent]           = acc[mi][nj2][0];
                        s_kv[(f + 1) * TSTRIDE + ent]     = acc[mi][nj2][1];
                        s_kv[f * TSTRIDE + ent + 8]       = acc[mi][nj2][2];
                        s_kv[(f + 1) * TSTRIDE + ent + 8] = acc[mi][nj2][3];
                    }
            }
            __syncthreads();
            {
                const int hl = warp >> 2;
                const int h  = ph * 2 + hl;
                const int e  = (warp & 3) * 32 + lane;
                float2 kvv[16];
#pragma unroll
                for (int d2 = 0; d2 < 16; ++d2) {
                    kvv[d2].x = s_kv[(hl * 32 + 2 * d2 + 0) * TSTRIDE + e];
                    kvv[d2].y = s_kv[(hl * 32 + 2 * d2 + 1) * TSTRIDE + e];
                }
#pragma unroll 2
                for (int q = 0; q < 16; ++q) {
                    const float* qrow = s_q + q * TSTRIDE + h * 32;
                    float2 a0 = make_float2(0.f, 0.f), a1 = make_float2(0.f, 0.f);
#pragma unroll
                    for (int d4 = 0; d4 < 8; ++d4) {
                        float4 q4 = *reinterpret_cast<const float4*>(qrow + d4 * 4);
                        a0 = ffma2(make_float2(q4.x, q4.y), kvv[d4 * 2 + 0], a0);
                        a1 = ffma2(make_float2(q4.z, q4.w), kvv[d4 * 2 + 1], a1);
                    }
                    s_w[(h * 16 + q) * 128 + e] = a0.x + a0.y + a1.x + a1.y;
                }
            }
            __syncthreads();
        }

        // ---- 8. masked softmax ----
        for (int it = 0; it < 8; ++it) {
            int pair = warp * 8 + it;
            int q = pair & 15;
            bool qmask = s_emf[q] > 0.5f;
            float lg[4];
#pragma unroll
            for (int j = 0; j < 4; ++j) {
                int k = lane + 32 * j;
                lg[j] = (qmask || s_emf[k] > 0.5f) ? -1e9f : s_w[pair * 128 + k];
            }
            float mx = fmaxf(fmaxf(lg[0], lg[1]), fmaxf(lg[2], lg[3]));
#pragma unroll
            for (int o = 16; o > 0; o >>= 1)
                mx = fmaxf(mx, __shfl_xor_sync(0xffffffffu, mx, o));
            float e[4];
            float sum = 0.f;
#pragma unroll
            for (int j = 0; j < 4; ++j) { e[j] = __expf(lg[j] - mx); sum += e[j]; }
#pragma unroll
            for (int o = 16; o > 0; o >>= 1)
                sum += __shfl_xor_sync(0xffffffffu, sum, o);
            bool allm = qmask || (s_flag[0] > 0.5f);
            float inv = allm ? 0.f : 1.f / sum;
#pragma unroll
            for (int j = 0; j < 4; ++j)
                s_w[pair * 128 + lane + 32 * j] = e[j] * inv;
        }
        CP_WAIT0();
        __syncthreads();

        // ---- 9. v GEMM ----
        gemm_mma<HE>(aL, bL, acc);
        __syncthreads();

        // ---- 10. two-phase vT write + attnV (s_attn overlays B; B dead) ----
#pragma unroll
        for (int ph = 0; ph < 2; ++ph) {
            if (nw == ph) {
#pragma unroll
                for (int mi = 0; mi < 2; ++mi)
#pragma unroll
                    for (int nj2 = 0; nj2 < 8; ++nj2) {
                        int ent = m0 + mi * 16 + (lane >> 2);
                        int f = nj2 * 8 + 2 * (lane & 3);
                        s_kv[f * TSTRIDE + ent]           = acc[mi][nj2][0];
                        s_kv[(f + 1) * TSTRIDE + ent]     = acc[mi][nj2][1];
                        s_kv[f * TSTRIDE + ent + 8]       = acc[mi][nj2][2];
                        s_kv[(f + 1) * TSTRIDE + ent + 8] = acc[mi][nj2][3];
                    }
            }
            __syncthreads();
            if ((cg >> 3) == ph) {
                const int h  = cq0 >> 5;
                const int lf = cq0 - ph * 64;
                float2 a2[8];
#pragma unroll
                for (int j = 0; j < 8; ++j) a2[j] = make_float2(0.f, 0.f);
                const float* wrow = s_w + (h * 16 + q16) * 128;
#pragma unroll 4
                for (int e0 = 0; e0 < NEN; e0 += 4) {
                    float4 w4 = *reinterpret_cast<const float4*>(wrow + e0);
                    float2 wlo = make_float2(w4.x, w4.y);
                    float2 whi = make_float2(w4.z, w4.w);
#pragma unroll
                    for (int jc = 0; jc < 8; ++jc) {
                        float4 v4 = *reinterpret_cast<const float4*>(&s_kv[(lf + jc) * TSTRIDE + e0]);
                        a2[jc] = ffma2(wlo, make_float2(v4.x, v4.y), a2[jc]);
                        a2[jc] = ffma2(whi, make_float2(v4.z, v4.w), a2[jc]);
                    }
                }
                float* ar = s_attn + q16 * TSTRIDE + cq0;
                *reinterpret_cast<float4*>(ar) = make_float4(
                    a2[0].x + a2[0].y, a2[1].x + a2[1].y, a2[2].x + a2[2].y, a2[3].x + a2[3].y);
                *reinterpret_cast<float4*>(ar + 4) = make_float4(
                    a2[4].x + a2[4].y, a2[5].x + a2[5].y, a2[6].x + a2[6].y, a2[7].x + a2[7].y);
            }
            __syncthreads();
        }

        // ---- 11. out = attn @ out_w + out_b, masked ----
        {
            float2 acc2[4];
#pragma unroll
            for (int j = 0; j < 4; ++j) acc2[j] = make_float2(0.f, 0.f);
            const float* Bo = outw + cq0;
#pragma unroll 4
            for (int k0 = 0; k0 < HE; k0 += 4) {
                float4 a4 = *reinterpret_cast<const float4*>(&s_attn[q16 * TSTRIDE + k0]);
                float av[4] = {a4.x, a4.y, a4.z, a4.w};
#pragma unroll
                for (int t = 0; t < 4; ++t) {
                    const float4* bp = reinterpret_cast<const float4*>(Bo + (k0 + t) * HE);
                    float4 b0 = __ldg(bp);
                    float4 b1 = __ldg(bp + 1);
                    float2 aa = make_float2(av[t], av[t]);
                    acc2[0] = ffma2(aa, make_float2(b0.x, b0.y), acc2[0]);
                    acc2[1] = ffma2(aa, make_float2(b0.z, b0.w), acc2[1]);
                    acc2[2] = ffma2(aa, make_float2(b1.x, b1.y), acc2[2]);
                    acc2[3] = ffma2(aa, make_float2(b1.z, b1.w), acc2[3]);
                }
            }
            float maskv = (s_emf[q16] > 0.5f) ? 0.f : 1.f;
            float4 ob0 = *reinterpret_cast<const float4*>(outb + cq0);
            float4 ob1 = *reinterpret_cast<const float4*>(outb + cq0 + 4);
            float* orow = s_out + q16 * TSTRIDE + cq0;
            __syncthreads();
            *reinterpret_cast<float4*>(orow) = make_float4(
                (acc2[0].x + ob0.x) * maskv, (acc2[0].y + ob0.y) * maskv,
                (acc2[1].x + ob0.z) * maskv, (acc2[1].y + ob0.w) * maskv);
            *reinterpret_cast<float4*>(orow + 4) = make_float4(
                (acc2[2].x + ob1.x) * maskv, (acc2[2].y + ob1.y) * maskv,
                (acc2[3].x + ob1.z) * maskv, (acc2[3].y + ob1.w) * maskv);
        }
        __syncthreads();

        // ---- 12. x3 = out @ fc2_w + fc2_b, masked ----
        {
            const int m0x = cg * 2;
            float2 acc2 = make_float2(0.f, 0.f);
#pragma unroll 8
            for (int k0 = 0; k0 < HE; k0 += 4) {
                float4 a4 = *reinterpret_cast<const float4*>(&s_out[q16 * TSTRIDE + k0]);
                float av[4] = {a4.x, a4.y, a4.z, a4.w};
#pragma unroll
                for (int t = 0; t < 4; ++t) {
                    float2 bw = __ldg(reinterpret_cast<const float2*>(fc2w + (k0 + t) * MD + m0x));
                    acc2 = ffma2(make_float2(av[t], av[t]), bw, acc2);
                }
            }
            float maskv = (s_emf[q16] > 0.5f) ? 0.f : 1.f;
            s_x3[q16 * MD + m0x]     = (acc2.x + fc2b[m0x])     * maskv;
            s_x3[q16 * MD + m0x + 1] = (acc2.y + fc2b[m0x + 1]) * maskv;
        }
        __syncthreads();

        if (tid < NA) {
            float s = 0.f;
#pragma unroll
            for (int m = 0; m < MD; ++m) s += s_x3[tid * MD + m];
            float rm = s * (1.f / MD);
            s_rm[tid] = rm;
            if (p == 0) s_w1m[tid] = rm;
        }
        __syncthreads();
    }

    if (tid == 0) {
        float vm = 0.f;
#pragma unroll
        for (int q = 0; q < NA; ++q) vm += s_rm[q];
        vm *= (1.f / NA);
        const float* qb = P.qs + (size_t)b * NA;
        float qt = 0.f;
#pragma unroll
        for (int a = 0; a < NA; ++a) qt += qb[a] * fabsf(s_w1m[a]);
        P.out[b] = qt + vm;
    }
}

extern "C" void kernel_launch(void* const* d_in, const int* in_sizes, int n_in,
                              void* d_out, int out_size) {
    KParams P;
    P.qs   = (const float*)d_in[0];
    P.ents = (const float*)d_in[1];
    P.em   = (const unsigned char*)d_in[2];
    for (int i = 0; i < 14; ++i) P.w[i] = (const float*)d_in[3 + i];
    P.out = (float*)d_out;

    cudaFuncSetAttribute(mixer_kernel, cudaFuncAttributeMaxDynamicSharedMemorySize, SMEM_BYTES);

    dim3 pgrid((128 * 16 + 255) / 256, 8);
    prep_kernel<<<pgrid, 256>>>(P);

    int nb = in_sizes[0] / NA;  // 1600
    mixer_kernel<<<nb, 256, SMEM_BYTES>>>(P);
}

// round 8
// speedup vs baseline: 2.5082x; 1.0835x over previous
#include <cuda_runtime.h>
#include <cuda_bf16.h>
#include <cstdint>

#define NA 16
#define NEN 128
#define ED 96
#define HE 128
#define MD 32
#define NH 4
#define HD 32
#define TSTRIDE 132   // fp32 stride (528B) for kv/q/attn/out
#define STRB 132      // u32 stride of bf16 A/B tiles (264 bf16 = 528B)
#define SWST 132      // s_w row stride (floats) — padded to kill bank conflicts

// ---- smem float offsets ----
#define OFF_A    0        // A tile: 128 x 264 bf16 = 67584B = 16896 floats
#define OFF_B    16896    // B tile: same
#define OFF_KV   33792    // 64 x 132 fp32 = 8448 floats (kT/vT half)
#define OFF_W    42240    // 64 x 132 fp32 = 8448 floats
#define OFF_Q    50688    // 16 x 132 fp32 = 2112
#define OFF_EMF  52800    // 128
#define OFF_RM   52928    // 16
#define OFF_W1   52944    // 16
#define OFF_FLAG 52960    // 1
#define SMEM_FLOATS 52968
#define SMEM_BYTES (SMEM_FLOATS * 4)

// overlays inside B region (B dead after v GEMM)
#define BOFF_ATTN 0
#define BOFF_OUT  8448
#define BOFF_X3   16896

#define TILE_U32 (128 * 132)

struct KParams {
    const float* qs;
    const float* ents;
    const unsigned char* em;
    const float* w[14];
    float* out;
};

// pre-split, pre-laid-out bf16 weight tiles: [p*4 + {fc1,q,k,v}]
__device__ uint32_t g_wt[8 * TILE_U32];

static __device__ __forceinline__ void split2(float a, float b, uint32_t& hi, uint32_t& lo) {
    __nv_bfloat16 ha = __float2bfloat16(a), hb = __float2bfloat16(b);
    float ra = a - __bfloat162float(ha), rb = b - __bfloat162float(hb);
    __nv_bfloat16 la = __float2bfloat16(ra), lb = __float2bfloat16(rb);
    hi = (uint32_t)__bfloat16_as_ushort(ha) | ((uint32_t)__bfloat16_as_ushort(hb) << 16);
    lo = (uint32_t)__bfloat16_as_ushort(la) | ((uint32_t)__bfloat16_as_ushort(lb) << 16);
}

static __device__ __forceinline__ float2 ffma2(float2 a, float2 b, float2 c) {
    unsigned long long au = *reinterpret_cast<unsigned long long*>(&a);
    unsigned long long bu = *reinterpret_cast<unsigned long long*>(&b);
    unsigned long long cu = *reinterpret_cast<unsigned long long*>(&c);
    asm("fma.rn.f32x2 %0, %1, %2, %0;" : "+l"(cu) : "l"(au), "l"(bu));
    return *reinterpret_cast<float2*>(&cu);
}

static __device__ __forceinline__ void ldmat4(uint32_t (&r)[4], uint32_t addr) {
    asm volatile("ldmatrix.sync.aligned.m8n8.x4.shared.b16 {%0,%1,%2,%3}, [%4];"
        : "=r"(r[0]), "=r"(r[1]), "=r"(r[2]), "=r"(r[3]) : "r"(addr));
}

static __device__ __forceinline__ void mma16816(float (&d)[4], const uint32_t (&a)[4],
                                                uint32_t b0, uint32_t b1) {
    asm volatile("mma.sync.aligned.m16n8k16.row.col.f32.bf16.bf16.f32 "
        "{%0,%1,%2,%3}, {%4,%5,%6,%7}, {%8,%9}, {%0,%1,%2,%3};"
        : "+f"(d[0]), "+f"(d[1]), "+f"(d[2]), "+f"(d[3])
        : "r"(a[0]), "r"(a[1]), "r"(a[2]), "r"(a[3]), "r"(b0), "r"(b1));
}

static __device__ __forceinline__ void cp_async16(uint32_t saddr, const void* g) {
    asm volatile("cp.async.cg.shared.global [%0], [%1], 16;" :: "r"(saddr), "l"(g));
}

static __device__ __forceinline__ void copyB_async(uint32_t bBase, const uint32_t* g, int tid) {
#pragma unroll 1
    for (int i = tid; i < TILE_U32 / 4; i += 256)
        cp_async16(bBase + (uint32_t)i * 16u, g + i * 4);
    asm volatile("cp.async.commit_group;" ::: "memory");
}
#define CP_WAIT0() asm volatile("cp.async.wait_group 0;" ::: "memory")

// Split-3 bf16 GEMM over A[128 x K(hi)|K(lo) bf16] x Bt[128 x K|K] (528B row stride).
// Fully unrolled so ptxas can hoist LDSMs across the k-steps of a pass.
template<int K>
static __device__ __forceinline__ void gemm_mma(uint32_t aL, uint32_t bL, float (&acc)[2][8][4]) {
#pragma unroll
    for (int i = 0; i < 2; ++i)
#pragma unroll
        for (int j = 0; j < 8; ++j)
#pragma unroll
            for (int r = 0; r < 4; ++r) acc[i][j][r] = 0.f;
#pragma unroll
    for (int pass = 0; pass < 3; ++pass) {
        const uint32_t aO = (pass == 2) ? (uint32_t)(K * 2) : 0u;  // bytes
        const uint32_t bO = (pass == 1) ? (uint32_t)(K * 2) : 0u;
#pragma unroll
        for (int kb = 0; kb < K * 2; kb += 32) {
            uint32_t a[2][4], bb[4][4];
            ldmat4(a[0], aL + aO + kb);
            ldmat4(a[1], aL + 16u * 528u + aO + kb);
#pragma unroll
            for (int nj = 0; nj < 4; ++nj)
                ldmat4(bb[nj], bL + (uint32_t)nj * 16u * 528u + bO + kb);
#pragma unroll
            for (int mi = 0; mi < 2; ++mi)
#pragma unroll
                for (int nj = 0; nj < 4; ++nj) {
                    mma16816(acc[mi][2 * nj],     a[mi], bb[nj][0], bb[nj][1]);
                    mma16816(acc[mi][2 * nj + 1], a[mi], bb[nj][2], bb[nj][3]);
                }
        }
    }
}

// ---- prep kernel: split weights into tile-image layout, once per launch ----
__global__ void prep_kernel(KParams P) {
    const int t = blockIdx.y;          // 0..7
    const int p = t >> 2, ch = t & 3;
    const float* W; int ldb, KP;
    if (ch == 0) { W = P.w[p * 7 + 0]; ldb = HE;     KP = ED / 2; }
    else         { W = P.w[p * 7 + 2] + (ch - 1) * HE; ldb = 3 * HE; KP = 64; }
    uint32_t* dst = g_wt + t * TILE_U32;
    const int nkpb = KP >> 2;
    int idx = blockIdx.x * blockDim.x + threadIdx.x;
    if (idx >= 128 * nkpb) return;
    int n = idx / nkpb, kpb = idx % nkpb;
    uint32_t hi[4], lo[4];
#pragma unroll
    for (int j = 0; j < 4; ++j) {
        int kp = kpb * 4 + j;
        float w0 = __ldg(W + (size_t)(2 * kp) * ldb + n);
        float w1 = __ldg(W + (size_t)(2 * kp + 1) * ldb + n);
        split2(w0, w1, hi[j], lo[j]);
    }
    *reinterpret_cast<uint4*>(dst + n * STRB + kpb * 4)      = make_uint4(hi[0], hi[1], hi[2], hi[3]);
    *reinterpret_cast<uint4*>(dst + n * STRB + KP + kpb * 4) = make_uint4(lo[0], lo[1], lo[2], lo[3]);
}

__global__ void __launch_bounds__(256, 1)
mixer_kernel(KParams P) {
    extern __shared__ float smem[];
    char*     smc   = reinterpret_cast<char*>(smem);
    uint32_t* Au    = reinterpret_cast<uint32_t*>(smem + OFF_A);
    float*    s_kv  = smem + OFF_KV;
    float*    s_w   = smem + OFF_W;
    float*    s_q   = smem + OFF_Q;
    float*    s_emf = smem + OFF_EMF;
    float*    s_rm  = smem + OFF_RM;
    float*    s_w1m = smem + OFF_W1;
    float*    s_flag= smem + OFF_FLAG;
    float*    s_attn= reinterpret_cast<float*>(smc + OFF_B * 4 + BOFF_ATTN);
    float*    s_out = reinterpret_cast<float*>(smc + OFF_B * 4 + BOFF_OUT);
    float*    s_x3  = reinterpret_cast<float*>(smc + OFF_B * 4 + BOFF_X3);

    __shared__ int s_wide;

    const int b    = blockIdx.x;
    const int tid  = threadIdx.x;
    const int lane = tid & 31;
    const int warp = tid >> 5;

    const int mw = warp & 3, nw = warp >> 2;
    const int m0 = mw * 32, n0 = nw * 64;

    const int q16 = tid & 15;
    const int cg  = tid >> 4;
    const int cq0 = cg * 8;

    uint32_t smem_u32;
    asm("{ .reg .u64 t; cvta.to.shared.u64 t, %1; cvt.u32.u64 %0, t; }"
        : "=r"(smem_u32) : "l"(smem));
    const uint32_t aBase = smem_u32 + OFF_A * 4;
    const uint32_t bBase = smem_u32 + OFF_B * 4;
    const uint32_t aL = aBase + (uint32_t)(m0 + (lane & 15)) * 528u + (uint32_t)(lane >> 4) * 16u;
    const uint32_t bL = bBase + (uint32_t)(n0 + (lane & 7) + ((lane & 16) >> 1)) * 528u
                              + (uint32_t)((lane >> 3) & 1) * 16u;

    // ---- mask dtype probe ----
    if (tid == 0) s_wide = 1;
    __syncthreads();
    {
        const unsigned* mwp = reinterpret_cast<const unsigned*>(P.em);
        bool ok = true;
#pragma unroll
        for (int s = 0; s < 4; ++s) {
            unsigned w = __ldg(mwp + tid + 256 * s);
            ok = ok && (w == 0u || w == 1u || w == 0x3F800000u);
        }
        if (!ok) atomicAnd(&s_wide, 0);
    }
    __syncthreads();
    const bool wide = (s_wide != 0);

    if (tid < NEN) {
        bool m;
        if (wide) m = __ldg(reinterpret_cast<const unsigned*>(P.em) + (size_t)b * NEN + tid) != 0u;
        else      m = __ldg(P.em + (size_t)b * NEN + tid) != 0;
        s_emf[tid] = m ? 1.0f : 0.0f;
    }
    __syncthreads();
    if (tid == 0) {
        bool all = true;
#pragma unroll
        for (int i = 0; i < NEN; ++i) all = all && (s_emf[i] > 0.5f);
        s_flag[0] = all ? 1.0f : 0.0f;
    }
    __syncthreads();

    float acc[2][8][4];

    for (int p = 0; p < 2; ++p) {
        const float* fc1b = P.w[p * 7 + 1];
        const float* outw = P.w[p * 7 + 3];
        const float* outb = P.w[p * 7 + 4];
        const float* fc2w = P.w[p * 7 + 5];
        const float* fc2b = P.w[p * 7 + 6];
        const uint32_t* wt = g_wt + (p * 4) * TILE_U32;

        // ---- 1. cp.async B(fc1) + fill A (ent hi|lo) ----
        copyB_async(bBase, wt, tid);
        {
            const float2* eg = reinterpret_cast<const float2*>(P.ents + (size_t)b * NEN * ED);
            for (int i = tid; i < NEN * (ED / 2); i += 256) {
                int e = i / (ED / 2), d2 = i % (ED / 2);
                float2 v = __ldg(eg + i);
                uint32_t hi, lo;
                split2(v.x, v.y, hi, lo);
                Au[e * STRB + d2]            = hi;
                Au[e * STRB + (ED / 2) + d2] = lo;
            }
        }
        CP_WAIT0();
        __syncthreads();

        // ---- 2. fc1 GEMM ----
        gemm_mma<ED>(aL, bL, acc);
        __syncthreads();

        // ---- 3. cp.async B(q) + x1 epilogue (relu+bias, re-split into A) ----
        copyB_async(bBase, wt + TILE_U32, tid);
#pragma unroll
        for (int mi = 0; mi < 2; ++mi)
#pragma unroll
            for (int nj2 = 0; nj2 < 8; ++nj2) {
                int r = m0 + mi * 16 + (lane >> 2);
                int c = n0 + nj2 * 8 + 2 * (lane & 3);
                float bias0 = __ldg(fc1b + c), bias1 = __ldg(fc1b + c + 1);
                float x0 = fmaxf(acc[mi][nj2][0] + bias0, 0.f);
                float x1v = fmaxf(acc[mi][nj2][1] + bias1, 0.f);
                uint32_t hi, lo;
                split2(x0, x1v, hi, lo);
                Au[r * STRB + (c >> 1)]      = hi;
                Au[r * STRB + 64 + (c >> 1)] = lo;
                x0  = fmaxf(acc[mi][nj2][2] + bias0, 0.f);
                x1v = fmaxf(acc[mi][nj2][3] + bias1, 0.f);
                split2(x0, x1v, hi, lo);
                Au[(r + 8) * STRB + (c >> 1)]      = hi;
                Au[(r + 8) * STRB + 64 + (c >> 1)] = lo;
            }
        CP_WAIT0();
        __syncthreads();

        // ---- 4. q GEMM ----
        gemm_mma<HE>(aL, bL, acc);
        __syncthreads();

        // ---- 5. cp.async B(k) + q epilogue ----
        copyB_async(bBase, wt + 2 * TILE_U32, tid);
        if (mw == 0) {
            const float qs = 0.17677669529663687f;  // 1/sqrt(32)
#pragma unroll
            for (int nj2 = 0; nj2 < 8; ++nj2) {
                int r = lane >> 2;
                int c = n0 + nj2 * 8 + 2 * (lane & 3);
                s_q[r * TSTRIDE + c]           = acc[0][nj2][0] * qs;
                s_q[r * TSTRIDE + c + 1]       = acc[0][nj2][1] * qs;
                s_q[(r + 8) * TSTRIDE + c]     = acc[0][nj2][2] * qs;
                s_q[(r + 8) * TSTRIDE + c + 1] = acc[0][nj2][3] * qs;
            }
        }
        CP_WAIT0();
        __syncthreads();

        // ---- 6. k GEMM ----
        gemm_mma<HE>(aL, bL, acc);
        __syncthreads();

        // ---- 7. cp.async B(v) overlapped with kT writes + logits ----
        copyB_async(bBase, wt + 3 * TILE_U32, tid);
#pragma unroll
        for (int ph = 0; ph < 2; ++ph) {
            if (nw == ph) {
#pragma unroll
                for (int mi = 0; mi < 2; ++mi)
#pragma unroll
                    for (int nj2 = 0; nj2 < 8; ++nj2) {
                        int ent = m0 + mi * 16 + (lane >> 2);
                        int f = nj2 * 8 + 2 * (lane & 3);
                        s_kv[f * TSTRIDE + ent]           = acc[mi][nj2][0];
                        s_kv[(f + 1) * TSTRIDE + ent]     = acc[mi][nj2][1];
                        s_kv[f * TSTRIDE + ent + 8]       = acc[mi][nj2][2];
                        s_kv[(f + 1) * TSTRIDE + ent + 8] = acc[mi][nj2][3];
                    }
            }
            __syncthreads();
            {
                const int hl = warp >> 2;
                const int h  = ph * 2 + hl;
                const int e  = (warp & 3) * 32 + lane;
                float2 kvv[16];
#pragma unroll
                for (int d2 = 0; d2 < 16; ++d2) {
                    kvv[d2].x = s_kv[(hl * 32 + 2 * d2 + 0) * TSTRIDE + e];
                    kvv[d2].y = s_kv[(hl * 32 + 2 * d2 + 1) * TSTRIDE + e];
                }
#pragma unroll 2
                for (int q = 0; q < 16; ++q) {
                    const float* qrow = s_q + q * TSTRIDE + h * 32;
                    float2 a0 = make_float2(0.f, 0.f), a1 = make_float2(0.f, 0.f);
#pragma unroll
                    for (int d4 = 0; d4 < 8; ++d4) {
                        float4 q4 = *reinterpret_cast<const float4*>(qrow + d4 * 4);
                        a0 = ffma2(make_float2(q4.x, q4.y), kvv[d4 * 2 + 0], a0);
                        a1 = ffma2(make_float2(q4.z, q4.w), kvv[d4 * 2 + 1], a1);
                    }
                    s_w[(h * 16 + q) * SWST + e] = a0.x + a0.y + a1.x + a1.y;
                }
            }
            __syncthreads();
        }

        // ---- 8. masked softmax ----
        for (int it = 0; it < 8; ++it) {
            int pair = warp * 8 + it;
            int q = pair & 15;
            bool qmask = s_emf[q] > 0.5f;
            float lg[4];
#pragma unroll
            for (int j = 0; j < 4; ++j) {
                int k = lane + 32 * j;
                lg[j] = (qmask || s_emf[k] > 0.5f) ? -1e9f : s_w[pair * SWST + k];
            }
            float mx = fmaxf(fmaxf(lg[0], lg[1]), fmaxf(lg[2], lg[3]));
#pragma unroll
            for (int o = 16; o > 0; o >>= 1)
                mx = fmaxf(mx, __shfl_xor_sync(0xffffffffu, mx, o));
            float e[4];
            float sum = 0.f;
#pragma unroll
            for (int j = 0; j < 4; ++j) { e[j] = __expf(lg[j] - mx); sum += e[j]; }
#pragma unroll
            for (int o = 16; o > 0; o >>= 1)
                sum += __shfl_xor_sync(0xffffffffu, sum, o);
            bool allm = qmask || (s_flag[0] > 0.5f);
            float inv = allm ? 0.f : 1.f / sum;
#pragma unroll
            for (int j = 0; j < 4; ++j)
                s_w[pair * SWST + lane + 32 * j] = e[j] * inv;
        }
        CP_WAIT0();
        __syncthreads();

        // ---- 9. v GEMM ----
        gemm_mma<HE>(aL, bL, acc);
        __syncthreads();

        // ---- 10. two-phase vT write + attnV (s_attn overlays B; B dead) ----
#pragma unroll
        for (int ph = 0; ph < 2; ++ph) {
            if (nw == ph) {
#pragma unroll
                for (int mi = 0; mi < 2; ++mi)
#pragma unroll
                    for (int nj2 = 0; nj2 < 8; ++nj2) {
                        int ent = m0 + mi * 16 + (lane >> 2);
                        int f = nj2 * 8 + 2 * (lane & 3);
                        s_kv[f * TSTRIDE + ent]           = acc[mi][nj2][0];
                        s_kv[(f + 1) * TSTRIDE + ent]     = acc[mi][nj2][1];
                        s_kv[f * TSTRIDE + ent + 8]       = acc[mi][nj2][2];
                        s_kv[(f + 1) * TSTRIDE + ent + 8] = acc[mi][nj2][3];
                    }
            }
            __syncthreads();
            if ((cg >> 3) == ph) {
                const int h  = cq0 >> 5;
                const int lf = cq0 - ph * 64;
                float2 a2[8];
#pragma unroll
                for (int j = 0; j < 8; ++j) a2[j] = make_float2(0.f, 0.f);
                const float* wrow = s_w + (h * 16 + q16) * SWST;
#pragma unroll 4
                for (int e0 = 0; e0 < NEN; e0 += 4) {
                    float4 w4 = *reinterpret_cast<const float4*>(wrow + e0);
                    float2 wlo = make_float2(w4.x, w4.y);
                    float2 whi = make_float2(w4.z, w4.w);
#pragma unroll
                    for (int jc = 0; jc < 8; ++jc) {
                        float4 v4 = *reinterpret_cast<const float4*>(&s_kv[(lf + jc) * TSTRIDE + e0]);
                        a2[jc] = ffma2(wlo, make_float2(v4.x, v4.y), a2[jc]);
                        a2[jc] = ffma2(whi, make_float2(v4.z, v4.w), a2[jc]);
                    }
                }
                float* ar = s_attn + q16 * TSTRIDE + cq0;
                *reinterpret_cast<float4*>(ar) = make_float4(
                    a2[0].x + a2[0].y, a2[1].x + a2[1].y, a2[2].x + a2[2].y, a2[3].x + a2[3].y);
                *reinterpret_cast<float4*>(ar + 4) = make_float4(
                    a2[4].x + a2[4].y, a2[5].x + a2[5].y, a2[6].x + a2[6].y, a2[7].x + a2[7].y);
            }
            __syncthreads();
        }

        // ---- 11. out = attn @ out_w + out_b, masked ----
        {
            float2 acc2[4];
#pragma unroll
            for (int j = 0; j < 4; ++j) acc2[j] = make_float2(0.f, 0.f);
            const float* Bo = outw + cq0;
#pragma unroll 4
            for (int k0 = 0; k0 < HE; k0 += 4) {
                float4 a4 = *reinterpret_cast<const float4*>(&s_attn[q16 * TSTRIDE + k0]);
                float av[4] = {a4.x, a4.y, a4.z, a4.w};
#pragma unroll
                for (int t = 0; t < 4; ++t) {
                    const float4* bp = reinterpret_cast<const float4*>(Bo + (k0 + t) * HE);
                    float4 b0 = __ldg(bp);
                    float4 b1 = __ldg(bp + 1);
                    float2 aa = make_float2(av[t], av[t]);
                    acc2[0] = ffma2(aa, make_float2(b0.x, b0.y), acc2[0]);
                    acc2[1] = ffma2(aa, make_float2(b0.z, b0.w), acc2[1]);
                    acc2[2] = ffma2(aa, make_float2(b1.x, b1.y), acc2[2]);
                    acc2[3] = ffma2(aa, make_float2(b1.z, b1.w), acc2[3]);
                }
            }
            float maskv = (s_emf[q16] > 0.5f) ? 0.f : 1.f;
            float4 ob0 = *reinterpret_cast<const float4*>(outb + cq0);
            float4 ob1 = *reinterpret_cast<const float4*>(outb + cq0 + 4);
            float* orow = s_out + q16 * TSTRIDE + cq0;
            __syncthreads();
            *reinterpret_cast<float4*>(orow) = make_float4(
                (acc2[0].x + ob0.x) * maskv, (acc2[0].y + ob0.y) * maskv,
                (acc2[1].x + ob0.z) * maskv, (acc2[1].y + ob0.w) * maskv);
            *reinterpret_cast<float4*>(orow + 4) = make_float4(
                (acc2[2].x + ob1.x) * maskv, (acc2[2].y + ob1.y) * maskv,
                (acc2[3].x + ob1.z) * maskv, (acc2[3].y + ob1.w) * maskv);
        }
        __syncthreads();

        // ---- 12. x3 = out @ fc2_w + fc2_b, masked ----
        {
            const int m0x = cg * 2;
            float2 acc2 = make_float2(0.f, 0.f);
#pragma unroll 8
            for (int k0 = 0; k0 < HE; k0 += 4) {
                float4 a4 = *reinterpret_cast<const float4*>(&s_out[q16 * TSTRIDE + k0]);
                float av[4] = {a4.x, a4.y, a4.z, a4.w};
#pragma unroll
                for (int t = 0; t < 4; ++t) {
                    float2 bw = __ldg(reinterpret_cast<const float2*>(fc2w + (k0 + t) * MD + m0x));
                    acc2 = ffma2(make_float2(av[t], av[t]), bw, acc2);
                }
            }
            float maskv = (s_emf[q16] > 0.5f) ? 0.f : 1.f;
            s_x3[q16 * MD + m0x]     = (acc2.x + fc2b[m0x])     * maskv;
            s_x3[q16 * MD + m0x + 1] = (acc2.y + fc2b[m0x + 1]) * maskv;
        }
        __syncthreads();

        if (tid < NA) {
            float s = 0.f;
#pragma unroll
            for (int m = 0; m < MD; ++m) s += s_x3[tid * MD + m];
            float rm = s * (1.f / MD);
            s_rm[tid] = rm;
            if (p == 0) s_w1m[tid] = rm;
        }
        __syncthreads();
    }

    if (tid == 0) {
        float vm = 0.f;
#pragma unroll
        for (int q = 0; q < NA; ++q) vm += s_rm[q];
        vm *= (1.f / NA);
        const float* qb = P.qs + (size_t)b * NA;
        float qt = 0.f;
#pragma unroll
        for (int a = 0; a < NA; ++a) qt += qb[a] * fabsf(s_w1m[a]);
        P.out[b] = qt + vm;
    }
}

extern "C" void kernel_launch(void* const* d_in, const int* in_sizes, int n_in,
                              void* d_out, int out_size) {
    KParams P;
    P.qs   = (const float*)d_in[0];
    P.ents = (const float*)d_in[1];
    P.em   = (const unsigned char*)d_in[2];
    for (int i = 0; i < 14; ++i) P.w[i] = (const float*)d_in[3 + i];
    P.out = (float*)d_out;

    cudaFuncSetAttribute(mixer_kernel, cudaFuncAttributeMaxDynamicSharedMemorySize, SMEM_BYTES);

    dim3 pgrid((128 * 16 + 255) / 256, 8);
    prep_kernel<<<pgrid, 256>>>(P);

    int nb = in_sizes[0] / NA;  // 1600
    mixer_kernel<<<nb, 256, SMEM_BYTES>>>(P);
}